// round 1
// baseline (speedup 1.0000x reference)
#include <cuda_runtime.h>
#include <math.h>
#include <stdint.h>

#define N_TOK 32768
#define DIM   512
#define NE    8
#define NF    2048
#define NCAP  4096

// ---------------- scratch (device globals; no allocs allowed) ----------------
__device__ float    g_logits[N_TOK * NE];
__device__ float    g_sumexp[NE];
__device__ unsigned g_thr[NE];
__device__ int      g_gcnt[NE];
__device__ int      g_needeq[NE];
__device__ int      g_idx[NE * NCAP];
__device__ float    g_vals[NE * NCAP];
__device__ int      g_slot[NE * N_TOK];
__device__ float    g_h[(size_t)NE * NCAP * NF];     // 256 MB
__device__ float    g_oute[(size_t)NE * NCAP * DIM]; // 64 MB

__device__ __forceinline__ unsigned fkey(float f) {
    unsigned u = __float_as_uint(f);
    return (u & 0x80000000u) ? ~u : (u | 0x80000000u);
}

// ---------------- K1: router logits [N, E] ----------------
__global__ __launch_bounds__(256) void k_logits(const float* __restrict__ x,
                                                const float* __restrict__ Wr) {
    __shared__ float sW[NE][DIM]; // transposed Wr
    int tid = threadIdx.x;
    for (int i = tid; i < DIM * NE; i += 256) {
        int d = i >> 3, e = i & 7; // Wr[d][e]
        sW[e][d] = Wr[i];
    }
    __syncthreads();
    int warp = tid >> 5, lane = tid & 31;
    int n = blockIdx.x * 8 + warp;
    const float* xr = x + (size_t)n * DIM;
    float acc[NE];
#pragma unroll
    for (int e = 0; e < NE; e++) acc[e] = 0.f;
    for (int d0 = 0; d0 < DIM; d0 += 32) {
        float xv = xr[d0 + lane];
#pragma unroll
        for (int e = 0; e < NE; e++) acc[e] += xv * sW[e][d0 + lane];
    }
#pragma unroll
    for (int e = 0; e < NE; e++) {
#pragma unroll
        for (int off = 16; off > 0; off >>= 1)
            acc[e] += __shfl_xor_sync(0xffffffffu, acc[e], off);
        if (lane == e) g_logits[n * NE + e] = acc[e];
    }
}

// ---------------- K2: per-expert sum(exp(logit)) ----------------
__global__ __launch_bounds__(1024) void k_sumexp() {
    int e = blockIdx.x, tid = threadIdx.x;
    float s = 0.f;
    for (int i = tid; i < N_TOK; i += 1024) s += expf(g_logits[i * NE + e]);
    __shared__ float red[32];
    int lane = tid & 31, w = tid >> 5;
#pragma unroll
    for (int off = 16; off > 0; off >>= 1) s += __shfl_xor_sync(0xffffffffu, s, off);
    if (lane == 0) red[w] = s;
    __syncthreads();
    if (w == 0) {
        float v = red[lane];
#pragma unroll
        for (int off = 16; off > 0; off >>= 1) v += __shfl_xor_sync(0xffffffffu, v, off);
        if (lane == 0) g_sumexp[e] = v;
    }
}

// ---------------- K3: per-expert radix select (top-NCAP threshold) ----------------
__global__ __launch_bounds__(1024) void k_select() {
    int e = blockIdx.x, tid = threadIdx.x;
    __shared__ int hist[256];
    __shared__ unsigned s_prefix;
    __shared__ int s_remaining, s_gcnt;
    if (tid == 0) { s_prefix = 0u; s_remaining = NCAP; s_gcnt = 0; }
    __syncthreads();
    for (int pass = 0; pass < 4; pass++) {
        int shift = 24 - 8 * pass;
        unsigned pmask = pass ? (0xFFFFFFFFu << (shift + 8)) : 0u;
        for (int i = tid; i < 256; i += 1024) hist[i] = 0;
        __syncthreads();
        unsigned pref = s_prefix;
        for (int i = tid; i < N_TOK; i += 1024) {
            unsigned k = fkey(g_logits[i * NE + e]);
            if ((k & pmask) == pref) atomicAdd(&hist[(k >> shift) & 255], 1);
        }
        __syncthreads();
        if (tid == 0) {
            int rem = s_remaining, above = 0, b = 255;
            for (; b >= 0; b--) {
                int h = hist[b];
                if (above + h >= rem) break;
                above += h;
            }
            s_gcnt += above;
            s_remaining = rem - above;
            s_prefix = pref | ((unsigned)b << shift);
        }
        __syncthreads();
    }
    if (tid == 0) {
        g_thr[e] = s_prefix;
        g_gcnt[e] = s_gcnt;
        g_needeq[e] = s_remaining;
    }
}

// ---------------- K4: deterministic compaction (jax tie-break: lower index) ----------------
__global__ __launch_bounds__(1024) void k_compact() {
    int e = blockIdx.x, tid = threadIdx.x;
    unsigned T = g_thr[e];
    int gcnt = g_gcnt[e], needeq = g_needeq[e];
    float inv = 1.0f / g_sumexp[e];
    __shared__ int wsum[32];
    int lane = tid & 31, w = tid >> 5;
    int base_gt = 0, base_eq = 0;
    for (int c0 = 0; c0 < N_TOK; c0 += 1024) {
        int n = c0 + tid;
        float lg = g_logits[n * NE + e];
        unsigned k = fkey(lg);
        int isgt = (k > T) ? 1 : 0;
        int iseq = (k == T) ? 1 : 0;
        int val = isgt | (iseq << 11);
        int v = val;
#pragma unroll
        for (int off = 1; off < 32; off <<= 1) {
            int u = __shfl_up_sync(0xffffffffu, v, off);
            if (lane >= off) v += u;
        }
        if (lane == 31) wsum[w] = v;
        __syncthreads();
        if (w == 0) {
            int t = wsum[lane];
#pragma unroll
            for (int off = 1; off < 32; off <<= 1) {
                int u = __shfl_up_sync(0xffffffffu, t, off);
                if (lane >= off) t += u;
            }
            wsum[lane] = t;
        }
        __syncthreads();
        int excl = ((w > 0) ? wsum[w - 1] : 0) + (v - val);
        int total = wsum[31];
        int ex_gt = excl & 0x7FF, ex_eq = excl >> 11;
        int slot = -1;
        if (isgt) slot = base_gt + ex_gt;
        else if (iseq) {
            int r = base_eq + ex_eq;
            if (r < needeq) slot = gcnt + r;
        }
        if (slot >= 0) {
            g_idx[e * NCAP + slot] = n;
            g_vals[e * NCAP + slot] = expf(lg) * inv;
        }
        g_slot[e * N_TOK + n] = slot;
        base_gt += total & 0x7FF;
        base_eq += total >> 11;
        __syncthreads();
    }
}

// ---------------- K5: GEMM1 (gathered A) + gelu -> g_h ----------------
__global__ __launch_bounds__(256) void k_gemm1(const float* __restrict__ x,
                                               const float* __restrict__ W1,
                                               const float* __restrict__ b1) {
    __shared__ float As[2][16][132];
    __shared__ float Bs[2][16][128];
    __shared__ int ridx[128];
    const int e = blockIdx.z;
    const int mBase = blockIdx.y * 128;
    const int fBase = blockIdx.x * 128;
    const int tid = threadIdx.x;
    if (tid < 128) ridx[tid] = g_idx[e * NCAP + mBase + tid];
    __syncthreads();
    const float* Bp = W1 + (size_t)e * DIM * NF + fBase;

    const int a_m  = tid >> 2;        // 0..63
    const int a_k4 = (tid & 3) * 4;   // 0,4,8,12
    const int b_k  = tid >> 5;        // 0..7
    const int b_f4 = (tid & 31) * 4;  // 0..124

    const float* arow0 = x + (size_t)ridx[a_m] * DIM + a_k4;
    const float* arow1 = x + (size_t)ridx[a_m + 64] * DIM + a_k4;

    float acc[8][8];
#pragma unroll
    for (int i = 0; i < 8; i++)
#pragma unroll
        for (int j = 0; j < 8; j++) acc[i][j] = 0.f;

    const int ty = tid >> 4, tx = tid & 15;
    const int rm = ty * 8, cn = tx * 8;

    float4 pa0 = *(const float4*)arow0;
    float4 pa1 = *(const float4*)arow1;
    float4 pb0 = *(const float4*)(Bp + (size_t)b_k * NF + b_f4);
    float4 pb1 = *(const float4*)(Bp + (size_t)(b_k + 8) * NF + b_f4);
    As[0][a_k4 + 0][a_m] = pa0.x; As[0][a_k4 + 1][a_m] = pa0.y;
    As[0][a_k4 + 2][a_m] = pa0.z; As[0][a_k4 + 3][a_m] = pa0.w;
    As[0][a_k4 + 0][a_m + 64] = pa1.x; As[0][a_k4 + 1][a_m + 64] = pa1.y;
    As[0][a_k4 + 2][a_m + 64] = pa1.z; As[0][a_k4 + 3][a_m + 64] = pa1.w;
    *(float4*)&Bs[0][b_k][b_f4] = pb0;
    *(float4*)&Bs[0][b_k + 8][b_f4] = pb1;
    __syncthreads();

    int buf = 0;
    const int KT = DIM / 16;
    for (int kt = 0; kt < KT; kt++) {
        if (kt + 1 < KT) {
            int kk = (kt + 1) * 16;
            pa0 = *(const float4*)(arow0 + kk);
            pa1 = *(const float4*)(arow1 + kk);
            pb0 = *(const float4*)(Bp + (size_t)(kk + b_k) * NF + b_f4);
            pb1 = *(const float4*)(Bp + (size_t)(kk + b_k + 8) * NF + b_f4);
        }
#pragma unroll
        for (int k = 0; k < 16; k++) {
            float4 ta0 = *(const float4*)&As[buf][k][rm];
            float4 ta1 = *(const float4*)&As[buf][k][rm + 4];
            float4 tb0 = *(const float4*)&Bs[buf][k][cn];
            float4 tb1 = *(const float4*)&Bs[buf][k][cn + 4];
            float a[8] = {ta0.x, ta0.y, ta0.z, ta0.w, ta1.x, ta1.y, ta1.z, ta1.w};
            float b[8] = {tb0.x, tb0.y, tb0.z, tb0.w, tb1.x, tb1.y, tb1.z, tb1.w};
#pragma unroll
            for (int i = 0; i < 8; i++)
#pragma unroll
                for (int j = 0; j < 8; j++) acc[i][j] += a[i] * b[j];
        }
        if (kt + 1 < KT) {
            int nb = buf ^ 1;
            As[nb][a_k4 + 0][a_m] = pa0.x; As[nb][a_k4 + 1][a_m] = pa0.y;
            As[nb][a_k4 + 2][a_m] = pa0.z; As[nb][a_k4 + 3][a_m] = pa0.w;
            As[nb][a_k4 + 0][a_m + 64] = pa1.x; As[nb][a_k4 + 1][a_m + 64] = pa1.y;
            As[nb][a_k4 + 2][a_m + 64] = pa1.z; As[nb][a_k4 + 3][a_m + 64] = pa1.w;
            *(float4*)&Bs[nb][b_k][b_f4] = pb0;
            *(float4*)&Bs[nb][b_k + 8][b_f4] = pb1;
        }
        __syncthreads();
        buf ^= 1;
    }

    const float* b1p = b1 + e * NF + fBase + cn;
#pragma unroll
    for (int i = 0; i < 8; i++) {
        float* orow = g_h + ((size_t)(e * NCAP + mBase + rm + i)) * NF + fBase + cn;
        float vj[8];
#pragma unroll
        for (int j = 0; j < 8; j++) {
            float v = acc[i][j] + b1p[j];
            vj[j] = 0.5f * v * (1.0f + erff(v * 0.70710678118654752f));
        }
        *(float4*)orow = make_float4(vj[0], vj[1], vj[2], vj[3]);
        *(float4*)(orow + 4) = make_float4(vj[4], vj[5], vj[6], vj[7]);
    }
}

// ---------------- K6: GEMM2 + bias + gate scale -> g_oute ----------------
__global__ __launch_bounds__(256) void k_gemm2(const float* __restrict__ W2,
                                               const float* __restrict__ b2) {
    __shared__ float As[2][16][132];
    __shared__ float Bs[2][16][128];
    const int e = blockIdx.z;
    const int mBase = blockIdx.y * 128;
    const int dBase = blockIdx.x * 128;
    const int tid = threadIdx.x;
    const float* Bp = W2 + (size_t)e * NF * DIM + dBase;

    const int a_m  = tid >> 2;
    const int a_k4 = (tid & 3) * 4;
    const int b_k  = tid >> 5;
    const int b_f4 = (tid & 31) * 4;

    const float* arow0 = g_h + ((size_t)(e * NCAP + mBase + a_m)) * NF + a_k4;
    const float* arow1 = g_h + ((size_t)(e * NCAP + mBase + a_m + 64)) * NF + a_k4;

    float acc[8][8];
#pragma unroll
    for (int i = 0; i < 8; i++)
#pragma unroll
        for (int j = 0; j < 8; j++) acc[i][j] = 0.f;

    const int ty = tid >> 4, tx = tid & 15;
    const int rm = ty * 8, cn = tx * 8;

    float4 pa0 = *(const float4*)arow0;
    float4 pa1 = *(const float4*)arow1;
    float4 pb0 = *(const float4*)(Bp + (size_t)b_k * DIM + b_f4);
    float4 pb1 = *(const float4*)(Bp + (size_t)(b_k + 8) * DIM + b_f4);
    As[0][a_k4 + 0][a_m] = pa0.x; As[0][a_k4 + 1][a_m] = pa0.y;
    As[0][a_k4 + 2][a_m] = pa0.z; As[0][a_k4 + 3][a_m] = pa0.w;
    As[0][a_k4 + 0][a_m + 64] = pa1.x; As[0][a_k4 + 1][a_m + 64] = pa1.y;
    As[0][a_k4 + 2][a_m + 64] = pa1.z; As[0][a_k4 + 3][a_m + 64] = pa1.w;
    *(float4*)&Bs[0][b_k][b_f4] = pb0;
    *(float4*)&Bs[0][b_k + 8][b_f4] = pb1;
    __syncthreads();

    int buf = 0;
    const int KT = NF / 16;
    for (int kt = 0; kt < KT; kt++) {
        if (kt + 1 < KT) {
            int kk = (kt + 1) * 16;
            pa0 = *(const float4*)(arow0 + kk);
            pa1 = *(const float4*)(arow1 + kk);
            pb0 = *(const float4*)(Bp + (size_t)(kk + b_k) * DIM + b_f4);
            pb1 = *(const float4*)(Bp + (size_t)(kk + b_k + 8) * DIM + b_f4);
        }
#pragma unroll
        for (int k = 0; k < 16; k++) {
            float4 ta0 = *(const float4*)&As[buf][k][rm];
            float4 ta1 = *(const float4*)&As[buf][k][rm + 4];
            float4 tb0 = *(const float4*)&Bs[buf][k][cn];
            float4 tb1 = *(const float4*)&Bs[buf][k][cn + 4];
            float a[8] = {ta0.x, ta0.y, ta0.z, ta0.w, ta1.x, ta1.y, ta1.z, ta1.w};
            float b[8] = {tb0.x, tb0.y, tb0.z, tb0.w, tb1.x, tb1.y, tb1.z, tb1.w};
#pragma unroll
            for (int i = 0; i < 8; i++)
#pragma unroll
                for (int j = 0; j < 8; j++) acc[i][j] += a[i] * b[j];
        }
        if (kt + 1 < KT) {
            int nb = buf ^ 1;
            As[nb][a_k4 + 0][a_m] = pa0.x; As[nb][a_k4 + 1][a_m] = pa0.y;
            As[nb][a_k4 + 2][a_m] = pa0.z; As[nb][a_k4 + 3][a_m] = pa0.w;
            As[nb][a_k4 + 0][a_m + 64] = pa1.x; As[nb][a_k4 + 1][a_m + 64] = pa1.y;
            As[nb][a_k4 + 2][a_m + 64] = pa1.z; As[nb][a_k4 + 3][a_m + 64] = pa1.w;
            *(float4*)&Bs[nb][b_k][b_f4] = pb0;
            *(float4*)&Bs[nb][b_k + 8][b_f4] = pb1;
        }
        __syncthreads();
        buf ^= 1;
    }

    const float* b2p = b2 + e * DIM + dBase + cn;
#pragma unroll
    for (int i = 0; i < 8; i++) {
        float sv = g_vals[e * NCAP + mBase + rm + i];
        float* orow = g_oute + ((size_t)(e * NCAP + mBase + rm + i)) * DIM + dBase + cn;
        float vj[8];
#pragma unroll
        for (int j = 0; j < 8; j++) vj[j] = (acc[i][j] + b2p[j]) * sv;
        *(float4*)orow = make_float4(vj[0], vj[1], vj[2], vj[3]);
        *(float4*)(orow + 4) = make_float4(vj[4], vj[5], vj[6], vj[7]);
    }
}

// ---------------- K7: deterministic gather-sum into output ----------------
__global__ __launch_bounds__(128) void k_combine(float* __restrict__ out) {
    int n = blockIdx.x;
    int tid = threadIdx.x;
    __shared__ int slots[NE];
    if (tid < NE) slots[tid] = g_slot[tid * N_TOK + n];
    __syncthreads();
    float4 acc = make_float4(0.f, 0.f, 0.f, 0.f);
#pragma unroll
    for (int e = 0; e < NE; e++) {
        int s = slots[e];
        if (s >= 0) {
            float4 v = *(const float4*)&g_oute[((size_t)(e * NCAP + s)) * DIM + tid * 4];
            acc.x += v.x; acc.y += v.y; acc.z += v.z; acc.w += v.w;
        }
    }
    ((float4*)out)[(size_t)n * (DIM / 4) + tid] = acc;
}

// ---------------- launch ----------------
extern "C" void kernel_launch(void* const* d_in, const int* in_sizes, int n_in,
                              void* d_out, int out_size) {
    const float* x  = (const float*)d_in[0];
    const float* Wr = (const float*)d_in[1];
    const float* W1 = (const float*)d_in[2];
    const float* b1 = (const float*)d_in[3];
    const float* W2 = (const float*)d_in[4];
    const float* b2 = (const float*)d_in[5];
    float* out = (float*)d_out;

    k_logits<<<N_TOK / 8, 256>>>(x, Wr);
    k_sumexp<<<NE, 1024>>>();
    k_select<<<NE, 1024>>>();
    k_compact<<<NE, 1024>>>();
    dim3 g1(NF / 128, NCAP / 128, NE);
    k_gemm1<<<g1, 256>>>(x, W1, b1);
    dim3 g2(DIM / 128, NCAP / 128, NE);
    k_gemm2<<<g2, 256>>>(W2, b2);
    k_combine<<<N_TOK, 128>>>(out);
}

// round 7
// speedup vs baseline: 1.9338x; 1.9338x over previous
#include <cuda_runtime.h>
#include <cuda_bf16.h>
#include <math.h>
#include <stdint.h>

#define N_TOK 32768
#define DIM   512
#define NE    8
#define NF    2048
#define NCAP  4096

// GEMM tiling
#define BM 128
#define BN 128
#define BKC 64
#define GTHREADS 512
// per-stage SMEM: Ah(16K) Al(16K) Bh(16K) Bl(16K) = 64K, double buffered
#define PART_BYTES 16384
#define STAGE_BYTES 65536
#define DYN_SMEM (2 * STAGE_BYTES)

// ---------------- scratch (device globals; no allocs allowed) ----------------
__device__ float    g_logits[N_TOK * NE];
__device__ float    g_sumexp[NE];
__device__ unsigned g_thr[NE];
__device__ int      g_gcnt[NE];
__device__ int      g_needeq[NE];
__device__ int      g_idx[NE * NCAP];
__device__ float    g_vals[NE * NCAP];
__device__ int      g_slot[NE * N_TOK];
__device__ __align__(16) __nv_bfloat16 g_xh[N_TOK * DIM];
__device__ __align__(16) __nv_bfloat16 g_xl[N_TOK * DIM];
__device__ __align__(16) __nv_bfloat16 g_w1th[NE * NF * DIM];   // [E][F][D]
__device__ __align__(16) __nv_bfloat16 g_w1tl[NE * NF * DIM];
__device__ __align__(16) __nv_bfloat16 g_w2th[NE * DIM * NF];   // [E][D][F]
__device__ __align__(16) __nv_bfloat16 g_w2tl[NE * DIM * NF];
__device__ __align__(16) __nv_bfloat16 g_hh[NE * NCAP * NF];
__device__ __align__(16) __nv_bfloat16 g_hl[NE * NCAP * NF];
__device__ __align__(16) float g_oute[(size_t)NE * NCAP * DIM];

// ---------------- helpers ----------------
__device__ __forceinline__ uint32_t smem_u32(const void* p) {
    uint32_t a;
    asm("{ .reg .u64 t; cvta.to.shared.u64 t, %1; cvt.u32.u64 %0, t; }" : "=r"(a) : "l"(p));
    return a;
}
#define SWZ(o) ((o) ^ (((o) >> 3) & 0x70))

#define CP_ASYNC16(saddr, gptr) \
    asm volatile("cp.async.cg.shared.global [%0], [%1], 16;" :: "r"(saddr), "l"(gptr))
#define CP_COMMIT() asm volatile("cp.async.commit_group;")
#define CP_WAIT1()  asm volatile("cp.async.wait_group 1;")

#define LDSM4(r, addr) \
    asm volatile("ldmatrix.sync.aligned.x4.m8n8.shared.b16 {%0,%1,%2,%3}, [%4];" \
        : "=r"((r)[0]), "=r"((r)[1]), "=r"((r)[2]), "=r"((r)[3]) : "r"(addr))

#define MMA_BF16(d, a, b0, b1) \
    asm volatile("mma.sync.aligned.m16n8k16.row.col.f32.bf16.bf16.f32 " \
        "{%0,%1,%2,%3},{%4,%5,%6,%7},{%8,%9},{%0,%1,%2,%3};" \
        : "+f"((d)[0]), "+f"((d)[1]), "+f"((d)[2]), "+f"((d)[3]) \
        : "r"((a)[0]), "r"((a)[1]), "r"((a)[2]), "r"((a)[3]), "r"(b0), "r"(b1))

__device__ __forceinline__ unsigned fkey(float f) {
    unsigned u = __float_as_uint(f);
    return (u & 0x80000000u) ? ~u : (u | 0x80000000u);
}

// ---------------- prep: split x -> bf16 hi/lo ----------------
__global__ __launch_bounds__(256) void k_split_x(const float* __restrict__ x) {
    size_t i = (size_t)blockIdx.x * 256 + threadIdx.x;
    float4 v = ((const float4*)x)[i];
    __nv_bfloat16 h0 = __float2bfloat16(v.x), h1 = __float2bfloat16(v.y);
    __nv_bfloat16 h2 = __float2bfloat16(v.z), h3 = __float2bfloat16(v.w);
    __nv_bfloat16 l0 = __float2bfloat16(v.x - __bfloat162float(h0));
    __nv_bfloat16 l1 = __float2bfloat16(v.y - __bfloat162float(h1));
    __nv_bfloat16 l2 = __float2bfloat16(v.z - __bfloat162float(h2));
    __nv_bfloat16 l3 = __float2bfloat16(v.w - __bfloat162float(h3));
    __nv_bfloat162* H = (__nv_bfloat162*)g_xh;
    __nv_bfloat162* L = (__nv_bfloat162*)g_xl;
    H[i * 2] = __halves2bfloat162(h0, h1); H[i * 2 + 1] = __halves2bfloat162(h2, h3);
    L[i * 2] = __halves2bfloat162(l0, l1); L[i * 2 + 1] = __halves2bfloat162(l2, l3);
}

// ---------------- prep: transpose [R,C] -> [C,R] with bf16 hi/lo split ----------------
__global__ void k_tsplit(const float* __restrict__ in, __nv_bfloat16* __restrict__ oh,
                         __nv_bfloat16* __restrict__ ol, int R, int C) {
    __shared__ float t[32][33];
    int e = blockIdx.z;
    const float* ip = in + (size_t)e * R * C;
    int c0 = blockIdx.x * 32, r0 = blockIdx.y * 32;
    for (int i = threadIdx.y; i < 32; i += 8)
        t[i][threadIdx.x] = ip[(size_t)(r0 + i) * C + c0 + threadIdx.x];
    __syncthreads();
    size_t ob = (size_t)e * R * C;
    for (int i = threadIdx.y; i < 32; i += 8) {
        float v = t[threadIdx.x][i];
        __nv_bfloat16 h = __float2bfloat16(v);
        size_t o = ob + (size_t)(c0 + i) * R + r0 + threadIdx.x;
        oh[o] = h;
        ol[o] = __float2bfloat16(v - __bfloat162float(h));
    }
}

// ---------------- K1: router logits [N, E] ----------------
__global__ __launch_bounds__(256) void k_logits(const float* __restrict__ x,
                                                const float* __restrict__ Wr) {
    __shared__ float sW[NE][DIM];
    int tid = threadIdx.x;
    for (int i = tid; i < DIM * NE; i += 256) {
        int d = i >> 3, e = i & 7;
        sW[e][d] = Wr[i];
    }
    __syncthreads();
    int warp = tid >> 5, lane = tid & 31;
    int n = blockIdx.x * 8 + warp;
    const float* xr = x + (size_t)n * DIM;
    float acc[NE];
#pragma unroll
    for (int e = 0; e < NE; e++) acc[e] = 0.f;
    for (int d0 = 0; d0 < DIM; d0 += 32) {
        float xv = xr[d0 + lane];
#pragma unroll
        for (int e = 0; e < NE; e++) acc[e] += xv * sW[e][d0 + lane];
    }
#pragma unroll
    for (int e = 0; e < NE; e++) {
#pragma unroll
        for (int off = 16; off > 0; off >>= 1)
            acc[e] += __shfl_xor_sync(0xffffffffu, acc[e], off);
        if (lane == e) g_logits[n * NE + e] = acc[e];
    }
}

// ---------------- K2: per-expert sum(exp(logit)) ----------------
__global__ __launch_bounds__(1024) void k_sumexp() {
    int e = blockIdx.x, tid = threadIdx.x;
    float s = 0.f;
    for (int i = tid; i < N_TOK; i += 1024) s += expf(g_logits[i * NE + e]);
    __shared__ float red[32];
    int lane = tid & 31, w = tid >> 5;
#pragma unroll
    for (int off = 16; off > 0; off >>= 1) s += __shfl_xor_sync(0xffffffffu, s, off);
    if (lane == 0) red[w] = s;
    __syncthreads();
    if (w == 0) {
        float v = red[lane];
#pragma unroll
        for (int off = 16; off > 0; off >>= 1) v += __shfl_xor_sync(0xffffffffu, v, off);
        if (lane == 0) g_sumexp[e] = v;
    }
}

// ---------------- K3: per-expert radix select ----------------
__global__ __launch_bounds__(1024) void k_select() {
    int e = blockIdx.x, tid = threadIdx.x;
    __shared__ int hist[256];
    __shared__ unsigned s_prefix;
    __shared__ int s_remaining, s_gcnt;
    if (tid == 0) { s_prefix = 0u; s_remaining = NCAP; s_gcnt = 0; }
    __syncthreads();
    for (int pass = 0; pass < 4; pass++) {
        int shift = 24 - 8 * pass;
        unsigned pmask = pass ? (0xFFFFFFFFu << (shift + 8)) : 0u;
        for (int i = tid; i < 256; i += 1024) hist[i] = 0;
        __syncthreads();
        unsigned pref = s_prefix;
        for (int i = tid; i < N_TOK; i += 1024) {
            unsigned k = fkey(g_logits[i * NE + e]);
            if ((k & pmask) == pref) atomicAdd(&hist[(k >> shift) & 255], 1);
        }
        __syncthreads();
        if (tid == 0) {
            int rem = s_remaining, above = 0, b = 255;
            for (; b >= 0; b--) {
                int h = hist[b];
                if (above + h >= rem) break;
                above += h;
            }
            s_gcnt += above;
            s_remaining = rem - above;
            s_prefix = pref | ((unsigned)b << shift);
        }
        __syncthreads();
    }
    if (tid == 0) {
        g_thr[e] = s_prefix;
        g_gcnt[e] = s_gcnt;
        g_needeq[e] = s_remaining;
    }
}

// ---------------- K4: deterministic compaction ----------------
__global__ __launch_bounds__(1024) void k_compact() {
    int e = blockIdx.x, tid = threadIdx.x;
    unsigned T = g_thr[e];
    int gcnt = g_gcnt[e], needeq = g_needeq[e];
    float inv = 1.0f / g_sumexp[e];
    __shared__ int wsum[32];
    int lane = tid & 31, w = tid >> 5;
    int base_gt = 0, base_eq = 0;
    for (int c0 = 0; c0 < N_TOK; c0 += 1024) {
        int n = c0 + tid;
        float lg = g_logits[n * NE + e];
        unsigned k = fkey(lg);
        int isgt = (k > T) ? 1 : 0;
        int iseq = (k == T) ? 1 : 0;
        int val = isgt | (iseq << 11);
        int v = val;
#pragma unroll
        for (int off = 1; off < 32; off <<= 1) {
            int u = __shfl_up_sync(0xffffffffu, v, off);
            if (lane >= off) v += u;
        }
        if (lane == 31) wsum[w] = v;
        __syncthreads();
        if (w == 0) {
            int t = wsum[lane];
#pragma unroll
            for (int off = 1; off < 32; off <<= 1) {
                int u = __shfl_up_sync(0xffffffffu, t, off);
                if (lane >= off) t += u;
            }
            wsum[lane] = t;
        }
        __syncthreads();
        int excl = ((w > 0) ? wsum[w - 1] : 0) + (v - val);
        int total = wsum[31];
        int ex_gt = excl & 0x7FF, ex_eq = excl >> 11;
        int slot = -1;
        if (isgt) slot = base_gt + ex_gt;
        else if (iseq) {
            int r = base_eq + ex_eq;
            if (r < needeq) slot = gcnt + r;
        }
        if (slot >= 0) {
            g_idx[e * NCAP + slot] = n;
            g_vals[e * NCAP + slot] = expf(lg) * inv;
        }
        g_slot[e * N_TOK + n] = slot;
        base_gt += total & 0x7FF;
        base_eq += total >> 11;
        __syncthreads();
    }
}

// ======================================================================
// GEMM core (mma.sync bf16, 3-product hi/lo split)
// CTA 128x128, BK=64, 512 threads, 16 warps of 32x32
// ======================================================================

// compute one BK=64 chunk from stage buffer into acc
__device__ __forceinline__ void mma_chunk(uint32_t sbase, int lane, int m0, int n0,
                                          float acc[2][4][4]) {
    const int lrow = lane & 15;
    const int ksel = (lane >> 4) * 16; // byte offset within k for this lane's 8x8
#pragma unroll
    for (int ks = 0; ks < 4; ks++) {
        uint32_t ahf[2][4], alf[2][4], bhf[2][4], blf[2][4];
        const int kb = ks * 32 + ksel;
#pragma unroll
        for (int am = 0; am < 2; am++) {
            uint32_t off = SWZ((uint32_t)((m0 + am * 16 + lrow) * 128 + kb));
            LDSM4(ahf[am], sbase + off);
            LDSM4(alf[am], sbase + PART_BYTES + off);
        }
#pragma unroll
        for (int bg = 0; bg < 2; bg++) {
            uint32_t off = SWZ((uint32_t)((n0 + bg * 16 + lrow) * 128 + kb));
            LDSM4(bhf[bg], sbase + 2 * PART_BYTES + off);
            LDSM4(blf[bg], sbase + 3 * PART_BYTES + off);
        }
#pragma unroll
        for (int am = 0; am < 2; am++)
#pragma unroll
            for (int na = 0; na < 4; na++) {
                int bg = na >> 1, j = na & 1;
                MMA_BF16(acc[am][na], ahf[am], bhf[bg][j], bhf[bg][j + 2]);
                MMA_BF16(acc[am][na], alf[am], bhf[bg][j], bhf[bg][j + 2]);
                MMA_BF16(acc[am][na], ahf[am], blf[bg][j], blf[bg][j + 2]);
            }
    }
}

// ---------------- K5: GEMM1 (gathered A) + gelu -> g_hh/g_hl ----------------
__global__ __launch_bounds__(GTHREADS, 1) void k_gemm1_mma(const float* __restrict__ b1) {
    extern __shared__ __align__(16) char dsm[];
    __shared__ int s_ridx[BM];
    const int tid = threadIdx.x;
    const int e = blockIdx.z;
    const int mBase = blockIdx.y * BM;
    const int fBase = blockIdx.x * BN;
    if (tid < BM) s_ridx[tid] = g_idx[e * NCAP + mBase + tid];
    __syncthreads();

    const uint32_t sb = smem_u32(dsm);
    const __nv_bfloat16* Wbh = g_w1th + ((size_t)e * NF + fBase) * DIM;
    const __nv_bfloat16* Wbl = g_w1tl + ((size_t)e * NF + fBase) * DIM;

    const int lane = tid & 31, wid = tid >> 5;
    const int m0 = (wid & 3) * 32, n0 = (wid >> 2) * 32;
    float acc[2][4][4];
#pragma unroll
    for (int a = 0; a < 2; a++)
#pragma unroll
        for (int b = 0; b < 4; b++)
#pragma unroll
            for (int cc = 0; cc < 4; cc++) acc[a][b][cc] = 0.f;

    const int NC = DIM / BKC; // 8
#define G1_LOAD(c, buf) do { \
    uint32_t stb = sb + (buf) * STAGE_BYTES; \
    _Pragma("unroll") \
    for (int it = 0; it < 8; it++) { \
        int part = it >> 1; \
        int idx = (it & 1) * 512 + tid; \
        int row = idx >> 3, seg = idx & 7; \
        uint32_t so = stb + part * PART_BYTES + SWZ((uint32_t)(row * 128 + seg * 16)); \
        const __nv_bfloat16* gp; \
        if (part == 0)      gp = g_xh + (size_t)s_ridx[row] * DIM + (c) * BKC + seg * 8; \
        else if (part == 1) gp = g_xl + (size_t)s_ridx[row] * DIM + (c) * BKC + seg * 8; \
        else if (part == 2) gp = Wbh + (size_t)row * DIM + (c) * BKC + seg * 8; \
        else                gp = Wbl + (size_t)row * DIM + (c) * BKC + seg * 8; \
        CP_ASYNC16(so, gp); \
    } \
} while (0)

    G1_LOAD(0, 0);
    CP_COMMIT();
    int buf = 0;
    for (int c = 0; c < NC; c++) {
        if (c + 1 < NC) G1_LOAD(c + 1, buf ^ 1);
        CP_COMMIT();
        CP_WAIT1();
        __syncthreads();
        mma_chunk(sb + buf * STAGE_BYTES, lane, m0, n0, acc);
        __syncthreads();
        buf ^= 1;
    }
#undef G1_LOAD

    // epilogue: bias + gelu + bf16 hi/lo split, direct stores
    const int r0 = lane >> 2, c0 = 2 * (lane & 3);
#pragma unroll
    for (int am = 0; am < 2; am++) {
        int gr0 = mBase + m0 + am * 16 + r0;
#pragma unroll
        for (int na = 0; na < 4; na++) {
            int gc = fBase + n0 + na * 8 + c0;
            float bb0 = b1[e * NF + gc], bb1 = b1[e * NF + gc + 1];
#pragma unroll
            for (int half = 0; half < 2; half++) {
                int gr = gr0 + half * 8;
                float v0 = acc[am][na][half * 2 + 0] + bb0;
                float v1 = acc[am][na][half * 2 + 1] + bb1;
                float gg0 = 0.5f * v0 * (1.0f + erff(v0 * 0.70710678118654752f));
                float gg1 = 0.5f * v1 * (1.0f + erff(v1 * 0.70710678118654752f));
                __nv_bfloat16 h0 = __float2bfloat16(gg0);
                __nv_bfloat16 h1 = __float2bfloat16(gg1);
                __nv_bfloat16 l0 = __float2bfloat16(gg0 - __bfloat162float(h0));
                __nv_bfloat16 l1 = __float2bfloat16(gg1 - __bfloat162float(h1));
                size_t o = ((size_t)(e * NCAP) + gr) * NF + gc;
                *(__nv_bfloat162*)(g_hh + o) = __halves2bfloat162(h0, h1);
                *(__nv_bfloat162*)(g_hl + o) = __halves2bfloat162(l0, l1);
            }
        }
    }
}

// ---------------- K6: GEMM2 + bias + gate -> g_oute ----------------
__global__ __launch_bounds__(GTHREADS, 1) void k_gemm2_mma(const float* __restrict__ b2) {
    extern __shared__ __align__(16) char dsm2[];
    const int tid = threadIdx.x;
    const int e = blockIdx.z;
    const int mBase = blockIdx.y * BM;
    const int dBase = blockIdx.x * BN;

    const uint32_t sb = smem_u32(dsm2);
    const __nv_bfloat16* Ahp = g_hh + ((size_t)(e * NCAP) + mBase) * NF;
    const __nv_bfloat16* Alp = g_hl + ((size_t)(e * NCAP) + mBase) * NF;
    const __nv_bfloat16* Wbh = g_w2th + ((size_t)e * DIM + dBase) * NF;
    const __nv_bfloat16* Wbl = g_w2tl + ((size_t)e * DIM + dBase) * NF;

    const int lane = tid & 31, wid = tid >> 5;
    const int m0 = (wid & 3) * 32, n0 = (wid >> 2) * 32;
    float acc[2][4][4];
#pragma unroll
    for (int a = 0; a < 2; a++)
#pragma unroll
        for (int b = 0; b < 4; b++)
#pragma unroll
            for (int cc = 0; cc < 4; cc++) acc[a][b][cc] = 0.f;

    const int NC = NF / BKC; // 32
#define G2_LOAD(c, buf) do { \
    uint32_t stb = sb + (buf) * STAGE_BYTES; \
    _Pragma("unroll") \
    for (int it = 0; it < 8; it++) { \
        int part = it >> 1; \
        int idx = (it & 1) * 512 + tid; \
        int row = idx >> 3, seg = idx & 7; \
        uint32_t so = stb + part * PART_BYTES + SWZ((uint32_t)(row * 128 + seg * 16)); \
        const __nv_bfloat16* gp; \
        if (part == 0)      gp = Ahp + (size_t)row * NF + (c) * BKC + seg * 8; \
        else if (part == 1) gp = Alp + (size_t)row * NF + (c) * BKC + seg * 8; \
        else if (part == 2) gp = Wbh + (size_t)row * NF + (c) * BKC + seg * 8; \
        else                gp = Wbl + (size_t)row * NF + (c) * BKC + seg * 8; \
        CP_ASYNC16(so, gp); \
    } \
} while (0)

    G2_LOAD(0, 0);
    CP_COMMIT();
    int buf = 0;
    for (int c = 0; c < NC; c++) {
        if (c + 1 < NC) G2_LOAD(c + 1, buf ^ 1);
        CP_COMMIT();
        CP_WAIT1();
        __syncthreads();
        mma_chunk(sb + buf * STAGE_BYTES, lane, m0, n0, acc);
        __syncthreads();
        buf ^= 1;
    }
#undef G2_LOAD

    const int r0 = lane >> 2, c0 = 2 * (lane & 3);
#pragma unroll
    for (int am = 0; am < 2; am++) {
        int gr0 = mBase + m0 + am * 16 + r0;
        float sv0 = g_vals[e * NCAP + gr0];
        float sv1 = g_vals[e * NCAP + gr0 + 8];
#pragma unroll
        for (int na = 0; na < 4; na++) {
            int gc = dBase + n0 + na * 8 + c0;
            float bb0 = b2[e * DIM + gc], bb1 = b2[e * DIM + gc + 1];
            size_t o0 = ((size_t)(e * NCAP) + gr0) * DIM + gc;
            size_t o1 = o0 + (size_t)8 * DIM;
            float2 w0 = make_float2((acc[am][na][0] + bb0) * sv0,
                                    (acc[am][na][1] + bb1) * sv0);
            float2 w1 = make_float2((acc[am][na][2] + bb0) * sv1,
                                    (acc[am][na][3] + bb1) * sv1);
            *(float2*)(g_oute + o0) = w0;
            *(float2*)(g_oute + o1) = w1;
        }
    }
}

// ---------------- K7: deterministic gather-sum into output ----------------
__global__ __launch_bounds__(128) void k_combine(float* __restrict__ out) {
    int n = blockIdx.x;
    int tid = threadIdx.x;
    __shared__ int slots[NE];
    if (tid < NE) slots[tid] = g_slot[tid * N_TOK + n];
    __syncthreads();
    float4 acc = make_float4(0.f, 0.f, 0.f, 0.f);
#pragma unroll
    for (int e = 0; e < NE; e++) {
        int s = slots[e];
        if (s >= 0) {
            float4 v = *(const float4*)&g_oute[((size_t)(e * NCAP + s)) * DIM + tid * 4];
            acc.x += v.x; acc.y += v.y; acc.z += v.z; acc.w += v.w;
        }
    }
    ((float4*)out)[(size_t)n * (DIM / 4) + tid] = acc;
}

// ---------------- launch ----------------
extern "C" void kernel_launch(void* const* d_in, const int* in_sizes, int n_in,
                              void* d_out, int out_size) {
    const float* x  = (const float*)d_in[0];
    const float* Wr = (const float*)d_in[1];
    const float* W1 = (const float*)d_in[2];
    const float* b1 = (const float*)d_in[3];
    const float* W2 = (const float*)d_in[4];
    const float* b2 = (const float*)d_in[5];
    float* out = (float*)d_out;

    static int configured = 0;
    cudaFuncSetAttribute(k_gemm1_mma, cudaFuncAttributeMaxDynamicSharedMemorySize, DYN_SMEM);
    cudaFuncSetAttribute(k_gemm2_mma, cudaFuncAttributeMaxDynamicSharedMemorySize, DYN_SMEM);
    (void)configured;

    // prep: bf16 hi/lo splits (+ weight transposes to K-major)
    k_split_x<<<(N_TOK * DIM / 4) / 256, 256>>>(x);
    {
        __nv_bfloat16 *w1h, *w1l, *w2h, *w2l;
        cudaGetSymbolAddress((void**)&w1h, g_w1th);
        cudaGetSymbolAddress((void**)&w1l, g_w1tl);
        cudaGetSymbolAddress((void**)&w2h, g_w2th);
        cudaGetSymbolAddress((void**)&w2l, g_w2tl);
        k_tsplit<<<dim3(NF / 32, DIM / 32, NE), dim3(32, 8)>>>(W1, w1h, w1l, DIM, NF);
        k_tsplit<<<dim3(DIM / 32, NF / 32, NE), dim3(32, 8)>>>(W2, w2h, w2l, NF, DIM);
    }

    k_logits<<<N_TOK / 8, 256>>>(x, Wr);
    k_sumexp<<<NE, 1024>>>();
    k_select<<<NE, 1024>>>();
    k_compact<<<NE, 1024>>>();

    k_gemm1_mma<<<dim3(NF / BN, NCAP / BM, NE), GTHREADS, DYN_SMEM>>>(b1);
    k_gemm2_mma<<<dim3(DIM / BN, NCAP / BM, NE), GTHREADS, DYN_SMEM>>>(b2);
    k_combine<<<N_TOK, 128>>>(out);
}

// round 11
// speedup vs baseline: 2.5899x; 1.3392x over previous
#include <cuda_runtime.h>
#include <cuda_fp16.h>
#include <math.h>
#include <stdint.h>

#define N_TOK 32768
#define DIM   512
#define NE    8
#define NF    2048
#define NCAP  4096

// GEMM tiling
#define BM 128
#define BN 128
#define BKC 64
#define GTHREADS 512
// per-stage SMEM: Ah(16K) Al(16K) B(16K) = 48K, 3 stages
#define PART_BYTES 16384
#define STAGE_BYTES 49152
#define NSTAGE 3
#define DYN_SMEM (NSTAGE * STAGE_BYTES)

// ---------------- scratch (device globals; no allocs allowed) ----------------
__device__ float    g_logits[N_TOK * NE];
__device__ float    g_sumexp[NE];
__device__ unsigned g_thr[NE];
__device__ int      g_gcnt[NE];
__device__ int      g_needeq[NE];
__device__ int      g_idx[NE * NCAP];
__device__ float    g_vals[NE * NCAP];
__device__ int      g_slot[NE * N_TOK];
__device__ __align__(16) __half g_xh[N_TOK * DIM];
__device__ __align__(16) __half g_xl[N_TOK * DIM];
__device__ __align__(16) __half g_w1t[NE * NF * DIM];   // [E][F][D] fp16
__device__ __align__(16) __half g_w2t[NE * DIM * NF];   // [E][D][F] fp16
__device__ __align__(16) __half g_hh[NE * NCAP * NF];
__device__ __align__(16) __half g_hl[NE * NCAP * NF];
__device__ __align__(16) float g_oute[(size_t)NE * NCAP * DIM];

// ---------------- helpers ----------------
__device__ __forceinline__ uint32_t smem_u32(const void* p) {
    uint32_t a;
    asm("{ .reg .u64 t; cvta.to.shared.u64 t, %1; cvt.u32.u64 %0, t; }" : "=r"(a) : "l"(p));
    return a;
}
#define SWZ(o) ((o) ^ (((o) >> 3) & 0x70))

#define CP_ASYNC16(saddr, gptr) \
    asm volatile("cp.async.cg.shared.global [%0], [%1], 16;" :: "r"(saddr), "l"(gptr))
#define CP_COMMIT() asm volatile("cp.async.commit_group;")
#define CP_WAIT1()  asm volatile("cp.async.wait_group 1;")

#define LDSM4(r, addr) \
    asm volatile("ldmatrix.sync.aligned.x4.m8n8.shared.b16 {%0,%1,%2,%3}, [%4];" \
        : "=r"((r)[0]), "=r"((r)[1]), "=r"((r)[2]), "=r"((r)[3]) : "r"(addr))

#define MMA_F16(d, a, b0, b1) \
    asm volatile("mma.sync.aligned.m16n8k16.row.col.f32.f16.f16.f32 " \
        "{%0,%1,%2,%3},{%4,%5,%6,%7},{%8,%9},{%0,%1,%2,%3};" \
        : "+f"((d)[0]), "+f"((d)[1]), "+f"((d)[2]), "+f"((d)[3]) \
        : "r"((a)[0]), "r"((a)[1]), "r"((a)[2]), "r"((a)[3]), "r"(b0), "r"(b1))

__device__ __forceinline__ unsigned fkey(float f) {
    unsigned u = __float_as_uint(f);
    return (u & 0x80000000u) ? ~u : (u | 0x80000000u);
}

// ---------------- prep: split x -> fp16 hi/lo ----------------
__global__ __launch_bounds__(256) void k_split_x(const float* __restrict__ x) {
    size_t i = (size_t)blockIdx.x * 256 + threadIdx.x;
    float4 v = ((const float4*)x)[i];
    __half h0 = __float2half_rn(v.x), h1 = __float2half_rn(v.y);
    __half h2 = __float2half_rn(v.z), h3 = __float2half_rn(v.w);
    __half l0 = __float2half_rn(v.x - __half2float(h0));
    __half l1 = __float2half_rn(v.y - __half2float(h1));
    __half l2 = __float2half_rn(v.z - __half2float(h2));
    __half l3 = __float2half_rn(v.w - __half2float(h3));
    __half2* H = (__half2*)g_xh;
    __half2* L = (__half2*)g_xl;
    H[i * 2] = __halves2half2(h0, h1); H[i * 2 + 1] = __halves2half2(h2, h3);
    L[i * 2] = __halves2half2(l0, l1); L[i * 2 + 1] = __halves2half2(l2, l3);
}

// ---------------- prep: transpose [R,C] -> [C,R] fp16 ----------------
__global__ void k_tsplit(const float* __restrict__ in, __half* __restrict__ oh,
                         int R, int C) {
    __shared__ float t[32][33];
    int e = blockIdx.z;
    const float* ip = in + (size_t)e * R * C;
    int c0 = blockIdx.x * 32, r0 = blockIdx.y * 32;
    for (int i = threadIdx.y; i < 32; i += 8)
        t[i][threadIdx.x] = ip[(size_t)(r0 + i) * C + c0 + threadIdx.x];
    __syncthreads();
    size_t ob = (size_t)e * R * C;
    for (int i = threadIdx.y; i < 32; i += 8) {
        float v = t[threadIdx.x][i];
        oh[ob + (size_t)(c0 + i) * R + r0 + threadIdx.x] = __float2half_rn(v);
    }
}

// ---------------- K1: router logits [N, E] (2 rows per warp) ----------------
__global__ __launch_bounds__(256) void k_logits(const float* __restrict__ x,
                                                const float* __restrict__ Wr) {
    __shared__ float sW[NE][DIM];
    int tid = threadIdx.x;
    for (int i = tid; i < DIM * NE; i += 256) {
        int d = i >> 3, e = i & 7;
        sW[e][d] = Wr[i];
    }
    __syncthreads();
    int warp = tid >> 5, lane = tid & 31;
    int n = blockIdx.x * 16 + warp * 2;
    const float* xr0 = x + (size_t)n * DIM;
    const float* xr1 = xr0 + DIM;
    float acc0[NE], acc1[NE];
#pragma unroll
    for (int e = 0; e < NE; e++) { acc0[e] = 0.f; acc1[e] = 0.f; }
    for (int d0 = 0; d0 < DIM; d0 += 32) {
        float a0 = xr0[d0 + lane];
        float a1 = xr1[d0 + lane];
#pragma unroll
        for (int e = 0; e < NE; e++) {
            float w = sW[e][d0 + lane];
            acc0[e] += a0 * w;
            acc1[e] += a1 * w;
        }
    }
#pragma unroll
    for (int e = 0; e < NE; e++) {
#pragma unroll
        for (int off = 16; off > 0; off >>= 1) {
            acc0[e] += __shfl_xor_sync(0xffffffffu, acc0[e], off);
            acc1[e] += __shfl_xor_sync(0xffffffffu, acc1[e], off);
        }
        if (lane == e) {
            g_logits[n * NE + e] = acc0[e];
            g_logits[(n + 1) * NE + e] = acc1[e];
        }
    }
}

// ---------------- K2: per-expert sum(exp(logit)) ----------------
__global__ __launch_bounds__(1024) void k_sumexp() {
    int e = blockIdx.x, tid = threadIdx.x;
    float s = 0.f;
    for (int i = tid; i < N_TOK; i += 1024) s += expf(g_logits[i * NE + e]);
    __shared__ float red[32];
    int lane = tid & 31, w = tid >> 5;
#pragma unroll
    for (int off = 16; off > 0; off >>= 1) s += __shfl_xor_sync(0xffffffffu, s, off);
    if (lane == 0) red[w] = s;
    __syncthreads();
    if (w == 0) {
        float v = red[lane];
#pragma unroll
        for (int off = 16; off > 0; off >>= 1) v += __shfl_xor_sync(0xffffffffu, v, off);
        if (lane == 0) g_sumexp[e] = v;
    }
}

// ---------------- K3: per-expert radix select ----------------
__global__ __launch_bounds__(1024) void k_select() {
    int e = blockIdx.x, tid = threadIdx.x;
    __shared__ int hist[256];
    __shared__ unsigned s_prefix;
    __shared__ int s_remaining, s_gcnt;
    if (tid == 0) { s_prefix = 0u; s_remaining = NCAP; s_gcnt = 0; }
    __syncthreads();
    for (int pass = 0; pass < 4; pass++) {
        int shift = 24 - 8 * pass;
        unsigned pmask = pass ? (0xFFFFFFFFu << (shift + 8)) : 0u;
        for (int i = tid; i < 256; i += 1024) hist[i] = 0;
        __syncthreads();
        unsigned pref = s_prefix;
        for (int i = tid; i < N_TOK; i += 1024) {
            unsigned k = fkey(g_logits[i * NE + e]);
            if ((k & pmask) == pref) atomicAdd(&hist[(k >> shift) & 255], 1);
        }
        __syncthreads();
        if (tid == 0) {
            int rem = s_remaining, above = 0, b = 255;
            for (; b >= 0; b--) {
                int h = hist[b];
                if (above + h >= rem) break;
                above += h;
            }
            s_gcnt += above;
            s_remaining = rem - above;
            s_prefix = pref | ((unsigned)b << shift);
        }
        __syncthreads();
    }
    if (tid == 0) {
        g_thr[e] = s_prefix;
        g_gcnt[e] = s_gcnt;
        g_needeq[e] = s_remaining;
    }
}

// ---------------- K4: deterministic compaction ----------------
__global__ __launch_bounds__(1024) void k_compact() {
    int e = blockIdx.x, tid = threadIdx.x;
    unsigned T = g_thr[e];
    int gcnt = g_gcnt[e], needeq = g_needeq[e];
    float inv = 1.0f / g_sumexp[e];
    __shared__ int wsum[32];
    int lane = tid & 31, w = tid >> 5;
    int base_gt = 0, base_eq = 0;
    for (int c0 = 0; c0 < N_TOK; c0 += 1024) {
        int n = c0 + tid;
        float lg = g_logits[n * NE + e];
        unsigned k = fkey(lg);
        int isgt = (k > T) ? 1 : 0;
        int iseq = (k == T) ? 1 : 0;
        int val = isgt | (iseq << 11);
        int v = val;
#pragma unroll
        for (int off = 1; off < 32; off <<= 1) {
            int u = __shfl_up_sync(0xffffffffu, v, off);
            if (lane >= off) v += u;
        }
        if (lane == 31) wsum[w] = v;
        __syncthreads();
        if (w == 0) {
            int t = wsum[lane];
#pragma unroll
            for (int off = 1; off < 32; off <<= 1) {
                int u = __shfl_up_sync(0xffffffffu, t, off);
                if (lane >= off) t += u;
            }
            wsum[lane] = t;
        }
        __syncthreads();
        int excl = ((w > 0) ? wsum[w - 1] : 0) + (v - val);
        int total = wsum[31];
        int ex_gt = excl & 0x7FF, ex_eq = excl >> 11;
        int slot = -1;
        if (isgt) slot = base_gt + ex_gt;
        else if (iseq) {
            int r = base_eq + ex_eq;
            if (r < needeq) slot = gcnt + r;
        }
        if (slot >= 0) {
            g_idx[e * NCAP + slot] = n;
            g_vals[e * NCAP + slot] = expf(lg) * inv;
        }
        g_slot[e * N_TOK + n] = slot;
        base_gt += total & 0x7FF;
        base_eq += total >> 11;
        __syncthreads();
    }
}

// ======================================================================
// GEMM core (mma.sync fp16, 2-product A-split)
// CTA 128x128, BK=64, 512 threads, 16 warps of 32x32, 3-stage cp.async
// ======================================================================

__device__ __forceinline__ void mma_chunk(uint32_t sbase, int lane, int m0, int n0,
                                          float acc[2][4][4]) {
    const int lrow = lane & 15;
    const int ksel = (lane >> 4) * 16;
#pragma unroll
    for (int ks = 0; ks < 4; ks++) {
        uint32_t ahf[2][4], alf[2][4], bhf[2][4];
        const int kb = ks * 32 + ksel;
#pragma unroll
        for (int am = 0; am < 2; am++) {
            uint32_t off = SWZ((uint32_t)((m0 + am * 16 + lrow) * 128 + kb));
            LDSM4(ahf[am], sbase + off);
            LDSM4(alf[am], sbase + PART_BYTES + off);
        }
#pragma unroll
        for (int bg = 0; bg < 2; bg++) {
            uint32_t off = SWZ((uint32_t)((n0 + bg * 16 + lrow) * 128 + kb));
            LDSM4(bhf[bg], sbase + 2 * PART_BYTES + off);
        }
#pragma unroll
        for (int am = 0; am < 2; am++)
#pragma unroll
            for (int na = 0; na < 4; na++) {
                int bg = na >> 1, j = na & 1;
                MMA_F16(acc[am][na], ahf[am], bhf[bg][j], bhf[bg][j + 2]);
                MMA_F16(acc[am][na], alf[am], bhf[bg][j], bhf[bg][j + 2]);
            }
    }
}

// ---------------- K5: GEMM1 (gathered A) + gelu -> g_hh/g_hl ----------------
__global__ __launch_bounds__(GTHREADS, 1) void k_gemm1_mma(const float* __restrict__ b1) {
    extern __shared__ __align__(16) char dsm[];
    __shared__ int s_ridx[BM];
    const int tid = threadIdx.x;
    const int e = blockIdx.z;
    const int mBase = blockIdx.y * BM;
    const int fBase = blockIdx.x * BN;
    if (tid < BM) s_ridx[tid] = g_idx[e * NCAP + mBase + tid];
    __syncthreads();

    const uint32_t sb = smem_u32(dsm);
    const __half* Wb = g_w1t + ((size_t)e * NF + fBase) * DIM;

    const int lane = tid & 31, wid = tid >> 5;
    const int m0 = (wid & 3) * 32, n0 = (wid >> 2) * 32;
    float acc[2][4][4];
#pragma unroll
    for (int a = 0; a < 2; a++)
#pragma unroll
        for (int b = 0; b < 4; b++)
#pragma unroll
            for (int cc = 0; cc < 4; cc++) acc[a][b][cc] = 0.f;

    const int NC = DIM / BKC; // 8
#define G1_LOAD(c, buf) do { \
    uint32_t stb = sb + (buf) * STAGE_BYTES; \
    _Pragma("unroll") \
    for (int it = 0; it < 6; it++) { \
        int part = it >> 1; \
        int idx = (it & 1) * 512 + tid; \
        int row = idx >> 3, seg = idx & 7; \
        uint32_t so = stb + part * PART_BYTES + SWZ((uint32_t)(row * 128 + seg * 16)); \
        const __half* gp; \
        if (part == 0)      gp = g_xh + (size_t)s_ridx[row] * DIM + (c) * BKC + seg * 8; \
        else if (part == 1) gp = g_xl + (size_t)s_ridx[row] * DIM + (c) * BKC + seg * 8; \
        else                gp = Wb + (size_t)row * DIM + (c) * BKC + seg * 8; \
        CP_ASYNC16(so, gp); \
    } \
} while (0)

    G1_LOAD(0, 0); CP_COMMIT();
    G1_LOAD(1, 1); CP_COMMIT();
    int s_mma = 0, s_ld = 2;
    for (int c = 0; c < NC; c++) {
        CP_WAIT1();
        __syncthreads();
        if (c + 2 < NC) G1_LOAD(c + 2, s_ld);
        CP_COMMIT();
        mma_chunk(sb + s_mma * STAGE_BYTES, lane, m0, n0, acc);
        s_mma = (s_mma == NSTAGE - 1) ? 0 : s_mma + 1;
        s_ld = (s_ld == NSTAGE - 1) ? 0 : s_ld + 1;
    }
#undef G1_LOAD

    // epilogue: bias + gelu + fp16 hi/lo split, direct stores
    const int r0 = lane >> 2, c0 = 2 * (lane & 3);
#pragma unroll
    for (int am = 0; am < 2; am++) {
        int gr0 = mBase + m0 + am * 16 + r0;
#pragma unroll
        for (int na = 0; na < 4; na++) {
            int gc = fBase + n0 + na * 8 + c0;
            float bb0 = b1[e * NF + gc], bb1 = b1[e * NF + gc + 1];
#pragma unroll
            for (int half = 0; half < 2; half++) {
                int gr = gr0 + half * 8;
                float v0 = acc[am][na][half * 2 + 0] + bb0;
                float v1 = acc[am][na][half * 2 + 1] + bb1;
                float gg0 = 0.5f * v0 * (1.0f + erff(v0 * 0.70710678118654752f));
                float gg1 = 0.5f * v1 * (1.0f + erff(v1 * 0.70710678118654752f));
                __half h0 = __float2half_rn(gg0);
                __half h1 = __float2half_rn(gg1);
                __half l0 = __float2half_rn(gg0 - __half2float(h0));
                __half l1 = __float2half_rn(gg1 - __half2float(h1));
                size_t o = ((size_t)(e * NCAP) + gr) * NF + gc;
                *(__half2*)(g_hh + o) = __halves2half2(h0, h1);
                *(__half2*)(g_hl + o) = __halves2half2(l0, l1);
            }
        }
    }
}

// ---------------- K6: GEMM2 + bias + gate -> g_oute ----------------
__global__ __launch_bounds__(GTHREADS, 1) void k_gemm2_mma(const float* __restrict__ b2) {
    extern __shared__ __align__(16) char dsm2[];
    const int tid = threadIdx.x;
    const int e = blockIdx.z;
    const int mBase = blockIdx.y * BM;
    const int dBase = blockIdx.x * BN;

    const uint32_t sb = smem_u32(dsm2);
    const __half* Ahp = g_hh + ((size_t)(e * NCAP) + mBase) * NF;
    const __half* Alp = g_hl + ((size_t)(e * NCAP) + mBase) * NF;
    const __half* Wb = g_w2t + ((size_t)e * DIM + dBase) * NF;

    const int lane = tid & 31, wid = tid >> 5;
    const int m0 = (wid & 3) * 32, n0 = (wid >> 2) * 32;
    float acc[2][4][4];
#pragma unroll
    for (int a = 0; a < 2; a++)
#pragma unroll
        for (int b = 0; b < 4; b++)
#pragma unroll
            for (int cc = 0; cc < 4; cc++) acc[a][b][cc] = 0.f;

    const int NC = NF / BKC; // 32
#define G2_LOAD(c, buf) do { \
    uint32_t stb = sb + (buf) * STAGE_BYTES; \
    _Pragma("unroll") \
    for (int it = 0; it < 6; it++) { \
        int part = it >> 1; \
        int idx = (it & 1) * 512 + tid; \
        int row = idx >> 3, seg = idx & 7; \
        uint32_t so = stb + part * PART_BYTES + SWZ((uint32_t)(row * 128 + seg * 16)); \
        const __half* gp; \
        if (part == 0)      gp = Ahp + (size_t)row * NF + (c) * BKC + seg * 8; \
        else if (part == 1) gp = Alp + (size_t)row * NF + (c) * BKC + seg * 8; \
        else                gp = Wb + (size_t)row * NF + (c) * BKC + seg * 8; \
        CP_ASYNC16(so, gp); \
    } \
} while (0)

    G2_LOAD(0, 0); CP_COMMIT();
    G2_LOAD(1, 1); CP_COMMIT();
    int s_mma = 0, s_ld = 2;
    for (int c = 0; c < NC; c++) {
        CP_WAIT1();
        __syncthreads();
        if (c + 2 < NC) G2_LOAD(c + 2, s_ld);
        CP_COMMIT();
        mma_chunk(sb + s_mma * STAGE_BYTES, lane, m0, n0, acc);
        s_mma = (s_mma == NSTAGE - 1) ? 0 : s_mma + 1;
        s_ld = (s_ld == NSTAGE - 1) ? 0 : s_ld + 1;
    }
#undef G2_LOAD

    const int r0 = lane >> 2, c0 = 2 * (lane & 3);
#pragma unroll
    for (int am = 0; am < 2; am++) {
        int gr0 = mBase + m0 + am * 16 + r0;
        float sv0 = g_vals[e * NCAP + gr0];
        float sv1 = g_vals[e * NCAP + gr0 + 8];
#pragma unroll
        for (int na = 0; na < 4; na++) {
            int gc = dBase + n0 + na * 8 + c0;
            float bb0 = b2[e * DIM + gc], bb1 = b2[e * DIM + gc + 1];
            size_t o0 = ((size_t)(e * NCAP) + gr0) * DIM + gc;
            size_t o1 = o0 + (size_t)8 * DIM;
            float2 w0 = make_float2((acc[am][na][0] + bb0) * sv0,
                                    (acc[am][na][1] + bb1) * sv0);
            float2 w1 = make_float2((acc[am][na][2] + bb0) * sv1,
                                    (acc[am][na][3] + bb1) * sv1);
            *(float2*)(g_oute + o0) = w0;
            *(float2*)(g_oute + o1) = w1;
        }
    }
}

// ---------------- K7: deterministic gather-sum into output ----------------
__global__ __launch_bounds__(128) void k_combine(float* __restrict__ out) {
    int n = blockIdx.x;
    int tid = threadIdx.x;
    __shared__ int slots[NE];
    if (tid < NE) slots[tid] = g_slot[tid * N_TOK + n];
    __syncthreads();
    float4 acc = make_float4(0.f, 0.f, 0.f, 0.f);
#pragma unroll
    for (int e = 0; e < NE; e++) {
        int s = slots[e];
        if (s >= 0) {
            float4 v = *(const float4*)&g_oute[((size_t)(e * NCAP + s)) * DIM + tid * 4];
            acc.x += v.x; acc.y += v.y; acc.z += v.z; acc.w += v.w;
        }
    }
    ((float4*)out)[(size_t)n * (DIM / 4) + tid] = acc;
}

// ---------------- launch ----------------
extern "C" void kernel_launch(void* const* d_in, const int* in_sizes, int n_in,
                              void* d_out, int out_size) {
    const float* x  = (const float*)d_in[0];
    const float* Wr = (const float*)d_in[1];
    const float* W1 = (const float*)d_in[2];
    const float* b1 = (const float*)d_in[3];
    const float* W2 = (const float*)d_in[4];
    const float* b2 = (const float*)d_in[5];
    float* out = (float*)d_out;

    cudaFuncSetAttribute(k_gemm1_mma, cudaFuncAttributeMaxDynamicSharedMemorySize, DYN_SMEM);
    cudaFuncSetAttribute(k_gemm2_mma, cudaFuncAttributeMaxDynamicSharedMemorySize, DYN_SMEM);

    // prep: fp16 splits / transposes
    k_split_x<<<(N_TOK * DIM / 4) / 256, 256>>>(x);
    {
        __half *w1t, *w2t;
        cudaGetSymbolAddress((void**)&w1t, g_w1t);
        cudaGetSymbolAddress((void**)&w2t, g_w2t);
        k_tsplit<<<dim3(NF / 32, DIM / 32, NE), dim3(32, 8)>>>(W1, w1t, DIM, NF);
        k_tsplit<<<dim3(DIM / 32, NF / 32, NE), dim3(32, 8)>>>(W2, w2t, NF, DIM);
    }

    k_logits<<<N_TOK / 16, 256>>>(x, Wr);
    k_sumexp<<<NE, 1024>>>();
    k_select<<<NE, 1024>>>();
    k_compact<<<NE, 1024>>>();

    k_gemm1_mma<<<dim3(NF / BN, NCAP / BM, NE), GTHREADS, DYN_SMEM>>>(b1);
    k_gemm2_mma<<<dim3(DIM / BN, NCAP / BM, NE), GTHREADS, DYN_SMEM>>>(b2);
    k_combine<<<N_TOK, 128>>>(out);
}

// round 14
// speedup vs baseline: 3.9996x; 1.5443x over previous
#include <cuda_runtime.h>
#include <cuda_fp16.h>
#include <math.h>
#include <stdint.h>

#define N_TOK 32768
#define DIM   512
#define NE    8
#define NF    2048
#define NCAP  4096

// GEMM tiling
#define BM 128
#define BN 128
#define BKC 64
#define GTHREADS 512
// per-stage SMEM: A(16K) B(16K) = 32K, 4 stages
#define PART_BYTES 16384
#define STAGE_BYTES 32768
#define NSTAGE 4
#define DYN_SMEM (NSTAGE * STAGE_BYTES)

// ---------------- scratch (device globals; no allocs allowed) ----------------
__device__ float    g_logits[N_TOK * NE];
__device__ float    g_sumexp[NE];
__device__ unsigned g_thr[NE];
__device__ int      g_gcnt[NE];
__device__ int      g_needeq[NE];
__device__ int      g_idx[NE * NCAP];
__device__ float    g_vals[NE * NCAP];
__device__ int      g_slot[NE * N_TOK];
__device__ __align__(16) __half g_xh[N_TOK * DIM];
__device__ __align__(16) __half g_w1t[NE * NF * DIM];   // [E][F][D] fp16
__device__ __align__(16) __half g_w2t[NE * DIM * NF];   // [E][D][F] fp16
__device__ __align__(16) __half g_hh[NE * NCAP * NF];
__device__ __align__(16) float g_oute[(size_t)NE * NCAP * DIM];

// ---------------- helpers ----------------
__device__ __forceinline__ uint32_t smem_u32(const void* p) {
    uint32_t a;
    asm("{ .reg .u64 t; cvta.to.shared.u64 t, %1; cvt.u32.u64 %0, t; }" : "=r"(a) : "l"(p));
    return a;
}
#define SWZ(o) ((o) ^ (((o) >> 3) & 0x70))

#define CP_ASYNC16(saddr, gptr) \
    asm volatile("cp.async.cg.shared.global [%0], [%1], 16;" :: "r"(saddr), "l"(gptr))
#define CP_COMMIT() asm volatile("cp.async.commit_group;")
#define CP_WAIT2()  asm volatile("cp.async.wait_group 2;")

#define LDSM4(r, addr) \
    asm volatile("ldmatrix.sync.aligned.x4.m8n8.shared.b16 {%0,%1,%2,%3}, [%4];" \
        : "=r"((r)[0]), "=r"((r)[1]), "=r"((r)[2]), "=r"((r)[3]) : "r"(addr))

#define MMA_F16(d, a, b0, b1) \
    asm volatile("mma.sync.aligned.m16n8k16.row.col.f32.f16.f16.f32 " \
        "{%0,%1,%2,%3},{%4,%5,%6,%7},{%8,%9},{%0,%1,%2,%3};" \
        : "+f"((d)[0]), "+f"((d)[1]), "+f"((d)[2]), "+f"((d)[3]) \
        : "r"((a)[0]), "r"((a)[1]), "r"((a)[2]), "r"((a)[3]), "r"(b0), "r"(b1))

__device__ __forceinline__ unsigned fkey(float f) {
    unsigned u = __float_as_uint(f);
    return (u & 0x80000000u) ? ~u : (u | 0x80000000u);
}

// ---------------- prep: x -> fp16 ----------------
__global__ __launch_bounds__(256) void k_split_x(const float* __restrict__ x) {
    size_t i = (size_t)blockIdx.x * 256 + threadIdx.x;
    float4 v = ((const float4*)x)[i];
    __half2 p0 = __halves2half2(__float2half_rn(v.x), __float2half_rn(v.y));
    __half2 p1 = __halves2half2(__float2half_rn(v.z), __float2half_rn(v.w));
    __half2* H = (__half2*)g_xh;
    H[i * 2] = p0;
    H[i * 2 + 1] = p1;
}

// ---------------- prep: transpose [R,C] -> [C,R] fp16 ----------------
__global__ void k_tsplit(const float* __restrict__ in, __half* __restrict__ oh,
                         int R, int C) {
    __shared__ float t[32][33];
    int e = blockIdx.z;
    const float* ip = in + (size_t)e * R * C;
    int c0 = blockIdx.x * 32, r0 = blockIdx.y * 32;
    for (int i = threadIdx.y; i < 32; i += 8)
        t[i][threadIdx.x] = ip[(size_t)(r0 + i) * C + c0 + threadIdx.x];
    __syncthreads();
    size_t ob = (size_t)e * R * C;
    for (int i = threadIdx.y; i < 32; i += 8) {
        float v = t[threadIdx.x][i];
        oh[ob + (size_t)(c0 + i) * R + r0 + threadIdx.x] = __float2half_rn(v);
    }
}

// ---------------- K1: router logits [N, E] (2 rows per warp) ----------------
__global__ __launch_bounds__(256) void k_logits(const float* __restrict__ x,
                                                const float* __restrict__ Wr) {
    __shared__ float sW[NE][DIM];
    int tid = threadIdx.x;
    for (int i = tid; i < DIM * NE; i += 256) {
        int d = i >> 3, e = i & 7;
        sW[e][d] = Wr[i];
    }
    __syncthreads();
    int warp = tid >> 5, lane = tid & 31;
    int n = blockIdx.x * 16 + warp * 2;
    const float* xr0 = x + (size_t)n * DIM;
    const float* xr1 = xr0 + DIM;
    float acc0[NE], acc1[NE];
#pragma unroll
    for (int e = 0; e < NE; e++) { acc0[e] = 0.f; acc1[e] = 0.f; }
    for (int d0 = 0; d0 < DIM; d0 += 32) {
        float a0 = xr0[d0 + lane];
        float a1 = xr1[d0 + lane];
#pragma unroll
        for (int e = 0; e < NE; e++) {
            float w = sW[e][d0 + lane];
            acc0[e] += a0 * w;
            acc1[e] += a1 * w;
        }
    }
#pragma unroll
    for (int e = 0; e < NE; e++) {
#pragma unroll
        for (int off = 16; off > 0; off >>= 1) {
            acc0[e] += __shfl_xor_sync(0xffffffffu, acc0[e], off);
            acc1[e] += __shfl_xor_sync(0xffffffffu, acc1[e], off);
        }
        if (lane == e) {
            g_logits[n * NE + e] = acc0[e];
            g_logits[(n + 1) * NE + e] = acc1[e];
        }
    }
}

// ---------------- K2: per-expert sum(exp(logit)) ----------------
__global__ __launch_bounds__(1024) void k_sumexp() {
    int e = blockIdx.x, tid = threadIdx.x;
    float s = 0.f;
    for (int i = tid; i < N_TOK; i += 1024) s += expf(g_logits[i * NE + e]);
    __shared__ float red[32];
    int lane = tid & 31, w = tid >> 5;
#pragma unroll
    for (int off = 16; off > 0; off >>= 1) s += __shfl_xor_sync(0xffffffffu, s, off);
    if (lane == 0) red[w] = s;
    __syncthreads();
    if (w == 0) {
        float v = red[lane];
#pragma unroll
        for (int off = 16; off > 0; off >>= 1) v += __shfl_xor_sync(0xffffffffu, v, off);
        if (lane == 0) g_sumexp[e] = v;
    }
}

// ---------------- K3: per-expert radix select ----------------
__global__ __launch_bounds__(1024) void k_select() {
    int e = blockIdx.x, tid = threadIdx.x;
    __shared__ int hist[256];
    __shared__ unsigned s_prefix;
    __shared__ int s_remaining, s_gcnt;
    if (tid == 0) { s_prefix = 0u; s_remaining = NCAP; s_gcnt = 0; }
    __syncthreads();
    for (int pass = 0; pass < 4; pass++) {
        int shift = 24 - 8 * pass;
        unsigned pmask = pass ? (0xFFFFFFFFu << (shift + 8)) : 0u;
        for (int i = tid; i < 256; i += 1024) hist[i] = 0;
        __syncthreads();
        unsigned pref = s_prefix;
        for (int i = tid; i < N_TOK; i += 1024) {
            unsigned k = fkey(g_logits[i * NE + e]);
            if ((k & pmask) == pref) atomicAdd(&hist[(k >> shift) & 255], 1);
        }
        __syncthreads();
        if (tid == 0) {
            int rem = s_remaining, above = 0, b = 255;
            for (; b >= 0; b--) {
                int h = hist[b];
                if (above + h >= rem) break;
                above += h;
            }
            s_gcnt += above;
            s_remaining = rem - above;
            s_prefix = pref | ((unsigned)b << shift);
        }
        __syncthreads();
    }
    if (tid == 0) {
        g_thr[e] = s_prefix;
        g_gcnt[e] = s_gcnt;
        g_needeq[e] = s_remaining;
    }
}

// ---------------- K4: deterministic compaction ----------------
__global__ __launch_bounds__(1024) void k_compact() {
    int e = blockIdx.x, tid = threadIdx.x;
    unsigned T = g_thr[e];
    int gcnt = g_gcnt[e], needeq = g_needeq[e];
    float inv = 1.0f / g_sumexp[e];
    __shared__ int wsum[32];
    int lane = tid & 31, w = tid >> 5;
    int base_gt = 0, base_eq = 0;
    for (int c0 = 0; c0 < N_TOK; c0 += 1024) {
        int n = c0 + tid;
        float lg = g_logits[n * NE + e];
        unsigned k = fkey(lg);
        int isgt = (k > T) ? 1 : 0;
        int iseq = (k == T) ? 1 : 0;
        int val = isgt | (iseq << 11);
        int v = val;
#pragma unroll
        for (int off = 1; off < 32; off <<= 1) {
            int u = __shfl_up_sync(0xffffffffu, v, off);
            if (lane >= off) v += u;
        }
        if (lane == 31) wsum[w] = v;
        __syncthreads();
        if (w == 0) {
            int t = wsum[lane];
#pragma unroll
            for (int off = 1; off < 32; off <<= 1) {
                int u = __shfl_up_sync(0xffffffffu, t, off);
                if (lane >= off) t += u;
            }
            wsum[lane] = t;
        }
        __syncthreads();
        int excl = ((w > 0) ? wsum[w - 1] : 0) + (v - val);
        int total = wsum[31];
        int ex_gt = excl & 0x7FF, ex_eq = excl >> 11;
        int slot = -1;
        if (isgt) slot = base_gt + ex_gt;
        else if (iseq) {
            int r = base_eq + ex_eq;
            if (r < needeq) slot = gcnt + r;
        }
        if (slot >= 0) {
            g_idx[e * NCAP + slot] = n;
            g_vals[e * NCAP + slot] = expf(lg) * inv;
        }
        g_slot[e * N_TOK + n] = slot;
        base_gt += total & 0x7FF;
        base_eq += total >> 11;
        __syncthreads();
    }
}

// ======================================================================
// GEMM core (mma.sync fp16 single product)
// CTA 128x128, BK=64, 512 threads, 16 warps of 32x32, 4-stage cp.async
// ======================================================================

__device__ __forceinline__ void mma_chunk(uint32_t sbase, int lane, int m0, int n0,
                                          float acc[2][4][4]) {
    const int lrow = lane & 15;
    const int ksel = (lane >> 4) * 16;
#pragma unroll
    for (int ks = 0; ks < 4; ks++) {
        uint32_t ahf[2][4], bhf[2][4];
        const int kb = ks * 32 + ksel;
#pragma unroll
        for (int am = 0; am < 2; am++) {
            uint32_t off = SWZ((uint32_t)((m0 + am * 16 + lrow) * 128 + kb));
            LDSM4(ahf[am], sbase + off);
        }
#pragma unroll
        for (int bg = 0; bg < 2; bg++) {
            uint32_t off = SWZ((uint32_t)((n0 + bg * 16 + lrow) * 128 + kb));
            LDSM4(bhf[bg], sbase + PART_BYTES + off);
        }
#pragma unroll
        for (int am = 0; am < 2; am++)
#pragma unroll
            for (int na = 0; na < 4; na++) {
                int bg = na >> 1, j = na & 1;
                MMA_F16(acc[am][na], ahf[am], bhf[bg][j], bhf[bg][j + 2]);
            }
    }
}

// ---------------- K5: GEMM1 (gathered A) + gelu -> g_hh ----------------
__global__ __launch_bounds__(GTHREADS, 1) void k_gemm1_mma(const float* __restrict__ b1) {
    extern __shared__ __align__(16) char dsm[];
    __shared__ int s_ridx[BM];
    const int tid = threadIdx.x;
    const int e = blockIdx.z;
    const int mBase = blockIdx.y * BM;
    const int fBase = blockIdx.x * BN;
    if (tid < BM) s_ridx[tid] = g_idx[e * NCAP + mBase + tid];
    __syncthreads();

    const uint32_t sb = smem_u32(dsm);
    const __half* Wb = g_w1t + ((size_t)e * NF + fBase) * DIM;

    const int lane = tid & 31, wid = tid >> 5;
    const int m0 = (wid & 3) * 32, n0 = (wid >> 2) * 32;
    float acc[2][4][4];
#pragma unroll
    for (int a = 0; a < 2; a++)
#pragma unroll
        for (int b = 0; b < 4; b++)
#pragma unroll
            for (int cc = 0; cc < 4; cc++) acc[a][b][cc] = 0.f;

    const int NC = DIM / BKC; // 8
#define G1_LOAD(c, buf) do { \
    uint32_t stb = sb + (buf) * STAGE_BYTES; \
    _Pragma("unroll") \
    for (int it = 0; it < 4; it++) { \
        int part = it >> 1; \
        int idx = (it & 1) * 512 + tid; \
        int row = idx >> 3, seg = idx & 7; \
        uint32_t so = stb + part * PART_BYTES + SWZ((uint32_t)(row * 128 + seg * 16)); \
        const __half* gp; \
        if (part == 0) gp = g_xh + (size_t)s_ridx[row] * DIM + (c) * BKC + seg * 8; \
        else           gp = Wb + (size_t)row * DIM + (c) * BKC + seg * 8; \
        CP_ASYNC16(so, gp); \
    } \
} while (0)

    G1_LOAD(0, 0); CP_COMMIT();
    G1_LOAD(1, 1); CP_COMMIT();
    G1_LOAD(2, 2); CP_COMMIT();
    int s_mma = 0, s_ld = 3;
    for (int c = 0; c < NC; c++) {
        CP_WAIT2();
        __syncthreads();
        if (c + 3 < NC) G1_LOAD(c + 3, s_ld);
        CP_COMMIT();
        mma_chunk(sb + s_mma * STAGE_BYTES, lane, m0, n0, acc);
        s_mma = (s_mma == NSTAGE - 1) ? 0 : s_mma + 1;
        s_ld = (s_ld == NSTAGE - 1) ? 0 : s_ld + 1;
        __syncthreads();
    }
#undef G1_LOAD

    // epilogue: bias + gelu + fp16, direct stores
    const int r0 = lane >> 2, c0 = 2 * (lane & 3);
#pragma unroll
    for (int am = 0; am < 2; am++) {
        int gr0 = mBase + m0 + am * 16 + r0;
#pragma unroll
        for (int na = 0; na < 4; na++) {
            int gc = fBase + n0 + na * 8 + c0;
            float bb0 = b1[e * NF + gc], bb1 = b1[e * NF + gc + 1];
#pragma unroll
            for (int half = 0; half < 2; half++) {
                int gr = gr0 + half * 8;
                float v0 = acc[am][na][half * 2 + 0] + bb0;
                float v1 = acc[am][na][half * 2 + 1] + bb1;
                float gg0 = 0.5f * v0 * (1.0f + erff(v0 * 0.70710678118654752f));
                float gg1 = 0.5f * v1 * (1.0f + erff(v1 * 0.70710678118654752f));
                size_t o = ((size_t)(e * NCAP) + gr) * NF + gc;
                *(__half2*)(g_hh + o) =
                    __halves2half2(__float2half_rn(gg0), __float2half_rn(gg1));
            }
        }
    }
}

// ---------------- K6: GEMM2 + bias + gate -> g_oute ----------------
__global__ __launch_bounds__(GTHREADS, 1) void k_gemm2_mma(const float* __restrict__ b2) {
    extern __shared__ __align__(16) char dsm2[];
    const int tid = threadIdx.x;
    const int e = blockIdx.z;
    const int mBase = blockIdx.y * BM;
    const int dBase = blockIdx.x * BN;

    const uint32_t sb = smem_u32(dsm2);
    const __half* Ahp = g_hh + ((size_t)(e * NCAP) + mBase) * NF;
    const __half* Wb = g_w2t + ((size_t)e * DIM + dBase) * NF;

    const int lane = tid & 31, wid = tid >> 5;
    const int m0 = (wid & 3) * 32, n0 = (wid >> 2) * 32;
    float acc[2][4][4];
#pragma unroll
    for (int a = 0; a < 2; a++)
#pragma unroll
        for (int b = 0; b < 4; b++)
#pragma unroll
            for (int cc = 0; cc < 4; cc++) acc[a][b][cc] = 0.f;

    const int NC = NF / BKC; // 32
#define G2_LOAD(c, buf) do { \
    uint32_t stb = sb + (buf) * STAGE_BYTES; \
    _Pragma("unroll") \
    for (int it = 0; it < 4; it++) { \
        int part = it >> 1; \
        int idx = (it & 1) * 512 + tid; \
        int row = idx >> 3, seg = idx & 7; \
        uint32_t so = stb + part * PART_BYTES + SWZ((uint32_t)(row * 128 + seg * 16)); \
        const __half* gp; \
        if (part == 0) gp = Ahp + (size_t)row * NF + (c) * BKC + seg * 8; \
        else           gp = Wb + (size_t)row * NF + (c) * BKC + seg * 8; \
        CP_ASYNC16(so, gp); \
    } \
} while (0)

    G2_LOAD(0, 0); CP_COMMIT();
    G2_LOAD(1, 1); CP_COMMIT();
    G2_LOAD(2, 2); CP_COMMIT();
    int s_mma = 0, s_ld = 3;
    for (int c = 0; c < NC; c++) {
        CP_WAIT2();
        __syncthreads();
        if (c + 3 < NC) G2_LOAD(c + 3, s_ld);
        CP_COMMIT();
        mma_chunk(sb + s_mma * STAGE_BYTES, lane, m0, n0, acc);
        s_mma = (s_mma == NSTAGE - 1) ? 0 : s_mma + 1;
        s_ld = (s_ld == NSTAGE - 1) ? 0 : s_ld + 1;
        __syncthreads();
    }
#undef G2_LOAD

    const int r0 = lane >> 2, c0 = 2 * (lane & 3);
#pragma unroll
    for (int am = 0; am < 2; am++) {
        int gr0 = mBase + m0 + am * 16 + r0;
        float sv0 = g_vals[e * NCAP + gr0];
        float sv1 = g_vals[e * NCAP + gr0 + 8];
#pragma unroll
        for (int na = 0; na < 4; na++) {
            int gc = dBase + n0 + na * 8 + c0;
            float bb0 = b2[e * DIM + gc], bb1 = b2[e * DIM + gc + 1];
            size_t o0 = ((size_t)(e * NCAP) + gr0) * DIM + gc;
            size_t o1 = o0 + (size_t)8 * DIM;
            float2 w0 = make_float2((acc[am][na][0] + bb0) * sv0,
                                    (acc[am][na][1] + bb1) * sv0);
            float2 w1 = make_float2((acc[am][na][2] + bb0) * sv1,
                                    (acc[am][na][3] + bb1) * sv1);
            *(float2*)(g_oute + o0) = w0;
            *(float2*)(g_oute + o1) = w1;
        }
    }
}

// ---------------- K7: deterministic gather-sum into output ----------------
__global__ __launch_bounds__(128) void k_combine(float* __restrict__ out) {
    int n = blockIdx.x;
    int tid = threadIdx.x;
    __shared__ int slots[NE];
    if (tid < NE) slots[tid] = g_slot[tid * N_TOK + n];
    __syncthreads();
    float4 acc = make_float4(0.f, 0.f, 0.f, 0.f);
#pragma unroll
    for (int e = 0; e < NE; e++) {
        int s = slots[e];
        if (s >= 0) {
            float4 v = *(const float4*)&g_oute[((size_t)(e * NCAP + s)) * DIM + tid * 4];
            acc.x += v.x; acc.y += v.y; acc.z += v.z; acc.w += v.w;
        }
    }
    ((float4*)out)[(size_t)n * (DIM / 4) + tid] = acc;
}

// ---------------- launch ----------------
extern "C" void kernel_launch(void* const* d_in, const int* in_sizes, int n_in,
                              void* d_out, int out_size) {
    const float* x  = (const float*)d_in[0];
    const float* Wr = (const float*)d_in[1];
    const float* W1 = (const float*)d_in[2];
    const float* b1 = (const float*)d_in[3];
    const float* W2 = (const float*)d_in[4];
    const float* b2 = (const float*)d_in[5];
    float* out = (float*)d_out;

    cudaFuncSetAttribute(k_gemm1_mma, cudaFuncAttributeMaxDynamicSharedMemorySize, DYN_SMEM);
    cudaFuncSetAttribute(k_gemm2_mma, cudaFuncAttributeMaxDynamicSharedMemorySize, DYN_SMEM);

    // prep: fp16 conversions / transposes
    k_split_x<<<(N_TOK * DIM / 4) / 256, 256>>>(x);
    {
        __half *w1t, *w2t;
        cudaGetSymbolAddress((void**)&w1t, g_w1t);
        cudaGetSymbolAddress((void**)&w2t, g_w2t);
        k_tsplit<<<dim3(NF / 32, DIM / 32, NE), dim3(32, 8)>>>(W1, w1t, DIM, NF);
        k_tsplit<<<dim3(DIM / 32, NF / 32, NE), dim3(32, 8)>>>(W2, w2t, NF, DIM);
    }

    k_logits<<<N_TOK / 16, 256>>>(x, Wr);
    k_sumexp<<<NE, 1024>>>();
    k_select<<<NE, 1024>>>();
    k_compact<<<NE, 1024>>>();

    k_gemm1_mma<<<dim3(NF / BN, NCAP / BM, NE), GTHREADS, DYN_SMEM>>>(b1);
    k_gemm2_mma<<<dim3(DIM / BN, NCAP / BM, NE), GTHREADS, DYN_SMEM>>>(b2);
    k_combine<<<N_TOK, 128>>>(out);
}

// round 15
// speedup vs baseline: 4.5348x; 1.1338x over previous
#include <cuda_runtime.h>
#include <cuda_fp16.h>
#include <math.h>
#include <stdint.h>

#define N_TOK 32768
#define DIM   512
#define NE    8
#define NF    2048
#define NCAP  4096

// GEMM tiling
#define BM 128
#define BN 256
#define BKC 64
#define GTHREADS 512
// per-stage SMEM: A(16K) B(32K) = 48K, 4 stages
#define PART_BYTES 16384
#define STAGE_BYTES 49152
#define NSTAGE 4
#define DYN_SMEM (NSTAGE * STAGE_BYTES)
#define OUTSCALE 256.0f
#define INV_OUTSCALE (1.0f / 256.0f)

// ---------------- scratch (device globals; no allocs allowed) ----------------
__device__ float    g_logits[NE * N_TOK];        // [E][N]
__device__ float    g_sumexp[NE];
__device__ float    g_partsum[NE][32];
__device__ int      g_hist[NE][256];
__device__ unsigned g_thr[NE];      // running prefix / final threshold key
__device__ int      g_gcnt[NE];     // running count of keys > threshold
__device__ int      g_needeq[NE];   // running remaining / final eq need
__device__ int      g_cnt[NE];      // atomic slot counter
__device__ int      g_eqcnt[NE];
__device__ int      g_eqbuf[NE * N_TOK];
__device__ int      g_idx[NE * NCAP];
__device__ float    g_vals[NE * NCAP];
__device__ int      g_slot[NE * N_TOK];
__device__ __align__(16) __half g_xh[N_TOK * DIM];
__device__ __align__(16) __half g_w1t[NE * NF * DIM];   // [E][F][D] fp16
__device__ __align__(16) __half g_w2t[NE * DIM * NF];   // [E][D][F] fp16
__device__ __align__(16) __half g_hh[NE * NCAP * NF];
__device__ __align__(16) __half g_oute[(size_t)NE * NCAP * DIM]; // x256 scaled

// ---------------- helpers ----------------
__device__ __forceinline__ uint32_t smem_u32(const void* p) {
    uint32_t a;
    asm("{ .reg .u64 t; cvta.to.shared.u64 t, %1; cvt.u32.u64 %0, t; }" : "=r"(a) : "l"(p));
    return a;
}
#define SWZ(o) ((o) ^ (((o) >> 3) & 0x70))

#define CP_ASYNC16(saddr, gptr) \
    asm volatile("cp.async.cg.shared.global [%0], [%1], 16;" :: "r"(saddr), "l"(gptr))
#define CP_COMMIT() asm volatile("cp.async.commit_group;")
#define CP_WAIT2()  asm volatile("cp.async.wait_group 2;")

#define LDSM4(r, addr) \
    asm volatile("ldmatrix.sync.aligned.x4.m8n8.shared.b16 {%0,%1,%2,%3}, [%4];" \
        : "=r"((r)[0]), "=r"((r)[1]), "=r"((r)[2]), "=r"((r)[3]) : "r"(addr))

#define MMA_F16(d, a, b0, b1) \
    asm volatile("mma.sync.aligned.m16n8k16.row.col.f32.f16.f16.f32 " \
        "{%0,%1,%2,%3},{%4,%5,%6,%7},{%8,%9},{%0,%1,%2,%3};" \
        : "+f"((d)[0]), "+f"((d)[1]), "+f"((d)[2]), "+f"((d)[3]) \
        : "r"((a)[0]), "r"((a)[1]), "r"((a)[2]), "r"((a)[3]), "r"(b0), "r"(b1))

__device__ __forceinline__ unsigned fkey(float f) {
    unsigned u = __float_as_uint(f);
    return (u & 0x80000000u) ? ~u : (u | 0x80000000u);
}

// ---------------- K1: fused x->fp16 + router logits ([E][N] layout) ----------------
__global__ __launch_bounds__(256) void k_prep_x(const float* __restrict__ x,
                                                const float* __restrict__ Wr) {
    __shared__ float sW[NE][DIM];
    int tid = threadIdx.x;
    for (int i = tid; i < DIM * NE; i += 256) {
        int d = i >> 3, e = i & 7; // Wr[d][e]
        sW[e][d] = Wr[i];
    }
    __syncthreads();
    int warp = tid >> 5, lane = tid & 31;
    int n = blockIdx.x * 16 + warp * 2;
    const float* xr0 = x + (size_t)n * DIM;
    const float* xr1 = xr0 + DIM;
    float acc0[NE], acc1[NE];
#pragma unroll
    for (int e = 0; e < NE; e++) { acc0[e] = 0.f; acc1[e] = 0.f; }
#pragma unroll
    for (int it = 0; it < 4; it++) {
        int d0 = it * 128 + lane * 4;
        float4 v0 = *(const float4*)(xr0 + d0);
        float4 v1 = *(const float4*)(xr1 + d0);
        // store fp16
        __half2 a01 = __halves2half2(__float2half_rn(v0.x), __float2half_rn(v0.y));
        __half2 a23 = __halves2half2(__float2half_rn(v0.z), __float2half_rn(v0.w));
        __half2 b01 = __halves2half2(__float2half_rn(v1.x), __float2half_rn(v1.y));
        __half2 b23 = __halves2half2(__float2half_rn(v1.z), __float2half_rn(v1.w));
        *(__half2*)(g_xh + (size_t)n * DIM + d0) = a01;
        *(__half2*)(g_xh + (size_t)n * DIM + d0 + 2) = a23;
        *(__half2*)(g_xh + (size_t)(n + 1) * DIM + d0) = b01;
        *(__half2*)(g_xh + (size_t)(n + 1) * DIM + d0 + 2) = b23;
#pragma unroll
        for (int e = 0; e < NE; e++) {
            float4 w = *(const float4*)&sW[e][d0];
            acc0[e] += v0.x * w.x + v0.y * w.y + v0.z * w.z + v0.w * w.w;
            acc1[e] += v1.x * w.x + v1.y * w.y + v1.z * w.z + v1.w * w.w;
        }
    }
#pragma unroll
    for (int e = 0; e < NE; e++) {
#pragma unroll
        for (int off = 16; off > 0; off >>= 1) {
            acc0[e] += __shfl_xor_sync(0xffffffffu, acc0[e], off);
            acc1[e] += __shfl_xor_sync(0xffffffffu, acc1[e], off);
        }
        if (lane == e) {
            g_logits[(size_t)e * N_TOK + n] = acc0[e];
            g_logits[(size_t)e * N_TOK + n + 1] = acc1[e];
        }
    }
}

// ---------------- prep: transpose [R,C] -> [C,R] fp16 ----------------
__global__ void k_tsplit(const float* __restrict__ in, __half* __restrict__ oh,
                         int R, int C) {
    __shared__ float t[32][33];
    int e = blockIdx.z;
    const float* ip = in + (size_t)e * R * C;
    int c0 = blockIdx.x * 32, r0 = blockIdx.y * 32;
    for (int i = threadIdx.y; i < 32; i += 8)
        t[i][threadIdx.x] = ip[(size_t)(r0 + i) * C + c0 + threadIdx.x];
    __syncthreads();
    size_t ob = (size_t)e * R * C;
    for (int i = threadIdx.y; i < 32; i += 8) {
        float v = t[threadIdx.x][i];
        oh[ob + (size_t)(c0 + i) * R + r0 + threadIdx.x] = __float2half_rn(v);
    }
}

// ---------------- K2: parallel radix histogram (pass 0 also computes sumexp) ----------------
__global__ __launch_bounds__(256) void k_hist(int pass) {
    int e = blockIdx.x, s = blockIdx.y, tid = threadIdx.x;
    __shared__ int hist[256];
    __shared__ float red[8];
    hist[tid] = 0;
    __syncthreads();
    int shift = 24 - 8 * pass;
    unsigned pmask = pass ? (0xFFFFFFFFu << (shift + 8)) : 0u;
    unsigned pref = pass ? g_thr[e] : 0u;
    float se = 0.f;
    const float* lp = g_logits + (size_t)e * N_TOK + s * 1024;
#pragma unroll
    for (int it = 0; it < 4; it++) {
        float lg = lp[it * 256 + tid];
        unsigned k = fkey(lg);
        if ((k & pmask) == pref) atomicAdd(&hist[(k >> shift) & 255], 1);
        if (pass == 0) se += expf(lg);
    }
    __syncthreads();
    if (hist[tid]) atomicAdd(&g_hist[e][tid], hist[tid]);
    if (pass == 0) {
        int lane = tid & 31, w = tid >> 5;
#pragma unroll
        for (int off = 16; off > 0; off >>= 1) se += __shfl_xor_sync(0xffffffffu, se, off);
        if (lane == 0) red[w] = se;
        __syncthreads();
        if (tid == 0) {
            float v = 0.f;
#pragma unroll
            for (int i = 0; i < 8; i++) v += red[i];
            g_partsum[e][s] = v;
        }
    }
}

// ---------------- K3: per-pass scan (pick bucket, update state, zero hist) ----------------
__global__ __launch_bounds__(256) void k_scan(int pass) {
    int e = blockIdx.x, tid = threadIdx.x;
    __shared__ int h[256];
    h[tid] = g_hist[e][tid];
    g_hist[e][tid] = 0;
    __syncthreads();
    if (tid == 0) {
        int rem = pass ? g_needeq[e] : NCAP;
        unsigned pref = pass ? g_thr[e] : 0u;
        int gc = pass ? g_gcnt[e] : 0;
        int shift = 24 - 8 * pass;
        int above = 0, b = 255;
        for (; b >= 0; b--) {
            int hh = h[b];
            if (above + hh >= rem) break;
            above += hh;
        }
        g_gcnt[e] = gc + above;
        g_needeq[e] = rem - above;
        g_thr[e] = pref | ((unsigned)b << shift);
        if (pass == 3) { g_cnt[e] = 0; g_eqcnt[e] = 0; }
    }
    if (pass == 0 && tid < 32) {
        float v = g_partsum[e][tid];
#pragma unroll
        for (int off = 16; off > 0; off >>= 1) v += __shfl_xor_sync(0xffffffffu, v, off);
        if (tid == 0) g_sumexp[e] = v;
    }
}

// ---------------- K4: parallel compaction (slot order free; eq deferred) ----------------
__global__ __launch_bounds__(256) void k_compact_par() {
    int e = blockIdx.x, s = blockIdx.y, tid = threadIdx.x;
    unsigned T = g_thr[e];
    float inv = 1.0f / g_sumexp[e];
    const float* lp = g_logits + (size_t)e * N_TOK;
#pragma unroll
    for (int it = 0; it < 4; it++) {
        int n = s * 1024 + it * 256 + tid;
        float lg = lp[n];
        unsigned k = fkey(lg);
        int slot = -1;
        if (k > T) {
            slot = atomicAdd(&g_cnt[e], 1);
            g_idx[e * NCAP + slot] = n;
            g_vals[e * NCAP + slot] = expf(lg) * inv;
            g_slot[(size_t)e * N_TOK + n] = slot;
        } else if (k == T) {
            int p = atomicAdd(&g_eqcnt[e], 1);
            g_eqbuf[(size_t)e * N_TOK + p] = n;
        } else {
            g_slot[(size_t)e * N_TOK + n] = -1;
        }
    }
}

// ---------------- K5: deterministic tie-break for threshold-equal tokens ----------------
__global__ __launch_bounds__(256) void k_eqfix() {
    int e = blockIdx.x, tid = threadIdx.x;
    int neq = g_eqcnt[e], need = g_needeq[e], base = g_gcnt[e];
    float inv = 1.0f / g_sumexp[e];
    const int* buf = g_eqbuf + (size_t)e * N_TOK;
    for (int i = tid; i < neq; i += 256) {
        int t = buf[i];
        int rank = 0;
        for (int j = 0; j < neq; j++) rank += (buf[j] < t) ? 1 : 0;
        int slot = -1;
        if (rank < need) {
            slot = base + rank;
            g_idx[e * NCAP + slot] = t;
            g_vals[e * NCAP + slot] = expf(g_logits[(size_t)e * N_TOK + t]) * inv;
        }
        g_slot[(size_t)e * N_TOK + t] = slot;
    }
}

// ======================================================================
// GEMM core (mma.sync fp16) — CTA 128x256, warp tile 32x64, 4-stage cp.async
// ======================================================================

__device__ __forceinline__ void mma_chunk(uint32_t sbase, int lane, int m0, int n0,
                                          float acc[2][8][4]) {
    const int lrow = lane & 15;
    const int ksel = (lane >> 4) * 16;
#pragma unroll
    for (int ks = 0; ks < 4; ks++) {
        uint32_t ahf[2][4], bhf[4][4];
        const int kb = ks * 32 + ksel;
#pragma unroll
        for (int am = 0; am < 2; am++) {
            uint32_t off = SWZ((uint32_t)((m0 + am * 16 + lrow) * 128 + kb));
            LDSM4(ahf[am], sbase + off);
        }
#pragma unroll
        for (int bg = 0; bg < 4; bg++) {
            uint32_t off = SWZ((uint32_t)((n0 + bg * 16 + lrow) * 128 + kb));
            LDSM4(bhf[bg], sbase + PART_BYTES + off);
        }
#pragma unroll
        for (int am = 0; am < 2; am++)
#pragma unroll
            for (int na = 0; na < 8; na++) {
                int bg = na >> 1, j = na & 1;
                MMA_F16(acc[am][na], ahf[am], bhf[bg][j], bhf[bg][j + 2]);
            }
    }
}

// ---------------- K6: GEMM1 (gathered A) + gelu -> g_hh ----------------
__global__ __launch_bounds__(GTHREADS) void k_gemm1_mma(const float* __restrict__ b1) {
    extern __shared__ __align__(16) char dsm[];
    __shared__ int s_ridx[BM];
    const int tid = threadIdx.x;
    const int e = blockIdx.z;
    const int mBase = blockIdx.y * BM;
    const int fBase = blockIdx.x * BN;
    if (tid < BM) s_ridx[tid] = g_idx[e * NCAP + mBase + tid];
    __syncthreads();

    const uint32_t sb = smem_u32(dsm);
    const __half* Wb = g_w1t + ((size_t)e * NF + fBase) * DIM;

    const int lane = tid & 31, wid = tid >> 5;
    const int m0 = (wid & 3) * 32, n0 = (wid >> 2) * 64;
    float acc[2][8][4];
#pragma unroll
    for (int a = 0; a < 2; a++)
#pragma unroll
        for (int b = 0; b < 8; b++)
#pragma unroll
            for (int cc = 0; cc < 4; cc++) acc[a][b][cc] = 0.f;

    const int NC = DIM / BKC; // 8
#define G1_LOAD(c, buf) do { \
    uint32_t stb = sb + (buf) * STAGE_BYTES; \
    _Pragma("unroll") \
    for (int it = 0; it < 2; it++) { \
        int idx = it * 512 + tid; \
        int row = idx >> 3, seg = idx & 7; \
        uint32_t so = stb + SWZ((uint32_t)(row * 128 + seg * 16)); \
        CP_ASYNC16(so, g_xh + (size_t)s_ridx[row] * DIM + (c) * BKC + seg * 8); \
    } \
    _Pragma("unroll") \
    for (int it = 0; it < 4; it++) { \
        int idx = it * 512 + tid; \
        int row = idx >> 3, seg = idx & 7; \
        uint32_t so = stb + PART_BYTES + SWZ((uint32_t)(row * 128 + seg * 16)); \
        CP_ASYNC16(so, Wb + (size_t)row * DIM + (c) * BKC + seg * 8); \
    } \
} while (0)

    G1_LOAD(0, 0); CP_COMMIT();
    G1_LOAD(1, 1); CP_COMMIT();
    G1_LOAD(2, 2); CP_COMMIT();
    int s_mma = 0, s_ld = 3;
    for (int c = 0; c < NC; c++) {
        CP_WAIT2();
        __syncthreads();
        if (c + 3 < NC) G1_LOAD(c + 3, s_ld);
        CP_COMMIT();
        mma_chunk(sb + s_mma * STAGE_BYTES, lane, m0, n0, acc);
        s_mma = (s_mma == NSTAGE - 1) ? 0 : s_mma + 1;
        s_ld = (s_ld == NSTAGE - 1) ? 0 : s_ld + 1;
    }
#undef G1_LOAD

    // epilogue: bias + gelu -> fp16
    const int r0 = lane >> 2, c0 = 2 * (lane & 3);
#pragma unroll
    for (int am = 0; am < 2; am++) {
        int gr0 = mBase + m0 + am * 16 + r0;
#pragma unroll
        for (int na = 0; na < 8; na++) {
            int gc = fBase + n0 + na * 8 + c0;
            float bb0 = b1[e * NF + gc], bb1 = b1[e * NF + gc + 1];
#pragma unroll
            for (int half = 0; half < 2; half++) {
                int gr = gr0 + half * 8;
                float v0 = acc[am][na][half * 2 + 0] + bb0;
                float v1 = acc[am][na][half * 2 + 1] + bb1;
                float gg0 = 0.5f * v0 * (1.0f + erff(v0 * 0.70710678118654752f));
                float gg1 = 0.5f * v1 * (1.0f + erff(v1 * 0.70710678118654752f));
                size_t o = ((size_t)(e * NCAP) + gr) * NF + gc;
                *(__half2*)(g_hh + o) =
                    __halves2half2(__float2half_rn(gg0), __float2half_rn(gg1));
            }
        }
    }
}

// ---------------- K7: GEMM2 + bias + gate -> g_oute (fp16, x256) ----------------
__global__ __launch_bounds__(GTHREADS) void k_gemm2_mma(const float* __restrict__ b2) {
    extern __shared__ __align__(16) char dsm2[];
    const int tid = threadIdx.x;
    const int e = blockIdx.z;
    const int mBase = blockIdx.y * BM;
    const int dBase = blockIdx.x * BN;

    const uint32_t sb = smem_u32(dsm2);
    const __half* Ahp = g_hh + ((size_t)(e * NCAP) + mBase) * NF;
    const __half* Wb = g_w2t + ((size_t)e * DIM + dBase) * NF;

    const int lane = tid & 31, wid = tid >> 5;
    const int m0 = (wid & 3) * 32, n0 = (wid >> 2) * 64;
    float acc[2][8][4];
#pragma unroll
    for (int a = 0; a < 2; a++)
#pragma unroll
        for (int b = 0; b < 8; b++)
#pragma unroll
            for (int cc = 0; cc < 4; cc++) acc[a][b][cc] = 0.f;

    const int NC = NF / BKC; // 32
#define G2_LOAD(c, buf) do { \
    uint32_t stb = sb + (buf) * STAGE_BYTES; \
    _Pragma("unroll") \
    for (int it = 0; it < 2; it++) { \
        int idx = it * 512 + tid; \
        int row = idx >> 3, seg = idx & 7; \
        uint32_t so = stb + SWZ((uint32_t)(row * 128 + seg * 16)); \
        CP_ASYNC16(so, Ahp + (size_t)row * NF + (c) * BKC + seg * 8); \
    } \
    _Pragma("unroll") \
    for (int it = 0; it < 4; it++) { \
        int idx = it * 512 + tid; \
        int row = idx >> 3, seg = idx & 7; \
        uint32_t so = stb + PART_BYTES + SWZ((uint32_t)(row * 128 + seg * 16)); \
        CP_ASYNC16(so, Wb + (size_t)row * NF + (c) * BKC + seg * 8); \
    } \
} while (0)

    G2_LOAD(0, 0); CP_COMMIT();
    G2_LOAD(1, 1); CP_COMMIT();
    G2_LOAD(2, 2); CP_COMMIT();
    int s_mma = 0, s_ld = 3;
    for (int c = 0; c < NC; c++) {
        CP_WAIT2();
        __syncthreads();
        if (c + 3 < NC) G2_LOAD(c + 3, s_ld);
        CP_COMMIT();
        mma_chunk(sb + s_mma * STAGE_BYTES, lane, m0, n0, acc);
        s_mma = (s_mma == NSTAGE - 1) ? 0 : s_mma + 1;
        s_ld = (s_ld == NSTAGE - 1) ? 0 : s_ld + 1;
    }
#undef G2_LOAD

    const int r0 = lane >> 2, c0 = 2 * (lane & 3);
#pragma unroll
    for (int am = 0; am < 2; am++) {
        int gr0 = mBase + m0 + am * 16 + r0;
        float sv0 = g_vals[e * NCAP + gr0] * OUTSCALE;
        float sv1 = g_vals[e * NCAP + gr0 + 8] * OUTSCALE;
#pragma unroll
        for (int na = 0; na < 8; na++) {
            int gc = dBase + n0 + na * 8 + c0;
            float bb0 = b2[e * DIM + gc], bb1 = b2[e * DIM + gc + 1];
            size_t o0 = ((size_t)(e * NCAP) + gr0) * DIM + gc;
            size_t o1 = o0 + (size_t)8 * DIM;
            *(__half2*)(g_oute + o0) =
                __halves2half2(__float2half_rn((acc[am][na][0] + bb0) * sv0),
                               __float2half_rn((acc[am][na][1] + bb1) * sv0));
            *(__half2*)(g_oute + o1) =
                __halves2half2(__float2half_rn((acc[am][na][2] + bb0) * sv1),
                               __float2half_rn((acc[am][na][3] + bb1) * sv1));
        }
    }
}

// ---------------- K8: deterministic gather-sum into output ----------------
__global__ __launch_bounds__(128) void k_combine(float* __restrict__ out) {
    int n = blockIdx.x;
    int tid = threadIdx.x;
    __shared__ int slots[NE];
    if (tid < NE) slots[tid] = g_slot[(size_t)tid * N_TOK + n];
    __syncthreads();
    float4 acc = make_float4(0.f, 0.f, 0.f, 0.f);
#pragma unroll
    for (int e = 0; e < NE; e++) {
        int s = slots[e];
        if (s >= 0) {
            const __half* p = g_oute + ((size_t)(e * NCAP + s)) * DIM + tid * 4;
            uint2 v = *(const uint2*)p;
            float2 fa = __half22float2(*(__half2*)&v.x);
            float2 fb = __half22float2(*(__half2*)&v.y);
            acc.x += fa.x; acc.y += fa.y; acc.z += fb.x; acc.w += fb.y;
        }
    }
    acc.x *= INV_OUTSCALE; acc.y *= INV_OUTSCALE;
    acc.z *= INV_OUTSCALE; acc.w *= INV_OUTSCALE;
    ((float4*)out)[(size_t)n * (DIM / 4) + tid] = acc;
}

// ---------------- launch ----------------
extern "C" void kernel_launch(void* const* d_in, const int* in_sizes, int n_in,
                              void* d_out, int out_size) {
    const float* x  = (const float*)d_in[0];
    const float* Wr = (const float*)d_in[1];
    const float* W1 = (const float*)d_in[2];
    const float* b1 = (const float*)d_in[3];
    const float* W2 = (const float*)d_in[4];
    const float* b2 = (const float*)d_in[5];
    float* out = (float*)d_out;

    cudaFuncSetAttribute(k_gemm1_mma, cudaFuncAttributeMaxDynamicSharedMemorySize, DYN_SMEM);
    cudaFuncSetAttribute(k_gemm2_mma, cudaFuncAttributeMaxDynamicSharedMemorySize, DYN_SMEM);

    k_prep_x<<<N_TOK / 16, 256>>>(x, Wr);
    {
        __half *w1t, *w2t;
        cudaGetSymbolAddress((void**)&w1t, g_w1t);
        cudaGetSymbolAddress((void**)&w2t, g_w2t);
        k_tsplit<<<dim3(NF / 32, DIM / 32, NE), dim3(32, 8)>>>(W1, w1t, DIM, NF);
        k_tsplit<<<dim3(DIM / 32, NF / 32, NE), dim3(32, 8)>>>(W2, w2t, NF, DIM);
    }

    for (int pass = 0; pass < 4; pass++) {
        k_hist<<<dim3(NE, 32), 256>>>(pass);
        k_scan<<<NE, 256>>>(pass);
    }
    k_compact_par<<<dim3(NE, 32), 256>>>();
    k_eqfix<<<NE, 256>>>();

    k_gemm1_mma<<<dim3(NF / BN, NCAP / BM, NE), GTHREADS, DYN_SMEM>>>(b1);
    k_gemm2_mma<<<dim3(DIM / BN, NCAP / BM, NE), GTHREADS, DYN_SMEM>>>(b2);
    k_combine<<<N_TOK, 128>>>(out);
}